// round 3
// baseline (speedup 1.0000x reference)
#include <cuda_runtime.h>
#include <math.h>

#define BB 8
#define NP 2048
#define EP 32768
#define NT (BB*NP)      // 16384 total nodes
#define ET (BB*EP)      // 262144 total edges
#define HH 128
#define NL 3
#define ES 50

typedef unsigned long long u64;

// ---- scratch (no allocations allowed; __device__ globals) ----
__device__ float g_state[NT*HH];   // node states
__device__ float g_S[NT*HH];       // state @ Wn1_top  (sender half)
__device__ float g_R[NT*HH];       // state @ Wn1_bot  (receiver half)
__device__ float g_msum[NT*HH];    // per-node message accumulator
__device__ int   g_off[BB];        // exclusive cumsum of num_nodes

__device__ __forceinline__ float sspf(float x){
    // softplus(x) - log(2), numerically stable
    return fmaxf(x, 0.0f) + log1pf(__expf(-fabsf(x))) - 0.69314718055994530942f;
}

// ---- packed f32x2 helpers (sm_100+) ----
__device__ __forceinline__ u64 pk2(float lo, float hi){
    u64 r; asm("mov.b64 %0, {%1, %2};" : "=l"(r) : "f"(lo), "f"(hi)); return r;
}
__device__ __forceinline__ void fma2(u64& d, u64 a, u64 b){
    asm("fma.rn.f32x2 %0, %1, %2, %3;" : "=l"(d) : "l"(a), "l"(b), "l"(d));
}
__device__ __forceinline__ float hadd2(u64 v){
    float lo, hi; asm("mov.b64 {%0, %1}, %2;" : "=f"(lo), "=f"(hi) : "l"(v));
    return lo + hi;
}

// ---------------------------------------------------------------------------
// init: node embedding gather + graph offsets
// ---------------------------------------------------------------------------
__global__ void k_init(const int* __restrict__ nodes, const float* __restrict__ emb,
                       const int* __restrict__ num_nodes){
    int i = blockIdx.x*blockDim.x + threadIdx.x;
    if (i == 0){
        int acc = 0;
        for (int b = 0; b < BB; b++){ g_off[b] = acc; acc += num_nodes[b]; }
    }
    if (i < NT*HH){
        int node = i >> 7, c = i & 127;
        g_state[i] = emb[nodes[node]*HH + c];
    }
}

__global__ void k_zero(){
    int i = blockIdx.x*blockDim.x + threadIdx.x;
    if (i < NT*HH) g_msum[i] = 0.0f;
}

// ---------------------------------------------------------------------------
// node pre-GEMM: S = state @ Wn1[:128], R = state @ Wn1[128:]
// 16 rows/block, 256 threads (threads <128 -> S cols, >=128 -> R cols)
// ---------------------------------------------------------------------------
__global__ void k_pre(const float* __restrict__ Wn1){
    __shared__ __align__(16) float As[16][HH];
    int t = threadIdx.x;
    int row0 = blockIdx.x*16;
    for (int i = t; i < 16*HH; i += 256)
        As[i>>7][i&127] = g_state[(row0 + (i>>7))*HH + (i&127)];
    __syncthreads();

    int half = t >> 7;
    int col  = t & 127;
    const float* W = Wn1 + half*HH*HH + col;
    float acc[16];
#pragma unroll
    for (int m = 0; m < 16; m++) acc[m] = 0.0f;
    for (int k = 0; k < HH; k += 4){
        float w0 = W[(k+0)*HH], w1 = W[(k+1)*HH], w2 = W[(k+2)*HH], w3 = W[(k+3)*HH];
#pragma unroll
        for (int m = 0; m < 16; m++){
            float4 a = *(const float4*)&As[m][k];
            acc[m] += a.x*w0 + a.y*w1 + a.z*w2 + a.w*w3;
        }
    }
    float* dst = half ? g_R : g_S;
#pragma unroll
    for (int m = 0; m < 16; m++) dst[(row0+m)*HH + col] = acc[m];
}

// ---------------------------------------------------------------------------
// edge kernel: per 16-edge tile, packed f32x2 math
//   A1 = ssp(S[snd] + R[rcv] + bn1)
//   A2 = ssp(gauss(d) @ We1 + be1)
//   msg = (A1@Wn2 + bn2) * ((A2@We2 + be2) * cut(d))
//   atomicAdd into g_msum[rcv]
// ---------------------------------------------------------------------------
__global__ void __launch_bounds__(128) k_edge(
    const int* __restrict__ atom_edges, const float* __restrict__ feats,
    const float* __restrict__ bn1, const float* __restrict__ Wn2, const float* __restrict__ bn2,
    const float* __restrict__ We1, const float* __restrict__ be1,
    const float* __restrict__ We2, const float* __restrict__ be2)
{
    __shared__ __align__(16) float As1[16][HH];
    __shared__ __align__(16) float As2[16][HH];
    __shared__ __align__(16) float es[16][ES];   // row stride 200B (8B aligned)
    __shared__ float sd[16];
    __shared__ int   ssnd[16], srcv[16];

    int t  = threadIdx.x;
    int e0 = blockIdx.x*16;
    if (t < 16){
        int e   = e0 + t;
        int off = g_off[e / EP];
        ssnd[t] = atom_edges[e*2+0] + off;
        srcv[t] = atom_edges[e*2+1] + off;
        sd[t]   = feats[e];
    }
    __syncthreads();

    // gaussian radial basis: exp(-(d-mu)^2 / (2*0.1^2))
    for (int i = t; i < 16*ES; i += 128){
        int m = i / ES, j = i % ES;
        float dd = sd[m] - 0.1f*(float)j;
        es[m][j] = __expf(-dd*dd*50.0f);
    }
    // A1 (one smem column per thread)
    {
        float b = bn1[t];
#pragma unroll
        for (int m = 0; m < 16; m++){
            float v = g_S[ssnd[m]*HH + t] + g_R[srcv[m]*HH + t] + b;
            As1[m][t] = sspf(v);
        }
    }
    __syncthreads();

    // A2 = ssp(es @ We1 + be1)   (packed over j pairs: 25 iterations)
    {
        u64 acc2[16];
#pragma unroll
        for (int m = 0; m < 16; m++) acc2[m] = 0ull;
        for (int j = 0; j < ES; j += 2){
            u64 w = pk2(We1[j*HH + t], We1[(j+1)*HH + t]);
#pragma unroll
            for (int m = 0; m < 16; m++){
                u64 e = *(const u64*)&es[m][j];
                fma2(acc2[m], e, w);
            }
        }
        float b = be1[t];
#pragma unroll
        for (int m = 0; m < 16; m++) As2[m][t] = sspf(hadd2(acc2[m]) + b);
    }
    __syncthreads();

    // dual GEMM (packed): message path and gate path in one K loop
    u64 mn2[16], gt2[16];
#pragma unroll
    for (int m = 0; m < 16; m++){ mn2[m] = 0ull; gt2[m] = 0ull; }
    for (int k = 0; k < HH; k += 4){
        u64 w1a = pk2(Wn2[(k+0)*HH+t], Wn2[(k+1)*HH+t]);
        u64 w1b = pk2(Wn2[(k+2)*HH+t], Wn2[(k+3)*HH+t]);
        u64 w2a = pk2(We2[(k+0)*HH+t], We2[(k+1)*HH+t]);
        u64 w2b = pk2(We2[(k+2)*HH+t], We2[(k+3)*HH+t]);
#pragma unroll
        for (int m = 0; m < 16; m++){
            ulonglong2 a1 = *(const ulonglong2*)&As1[m][k];
            ulonglong2 a2 = *(const ulonglong2*)&As2[m][k];
            fma2(mn2[m], a1.x, w1a);
            fma2(mn2[m], a1.y, w1b);
            fma2(gt2[m], a2.x, w2a);
            fma2(gt2[m], a2.y, w2b);
        }
    }
    float b2 = bn2[t], be2v = be2[t];
#pragma unroll
    for (int m = 0; m < 16; m++){
        float d   = sd[m];
        float cut = 1.0f/(1.0f + __expf(5.0f*(d - 3.5f)));   // 1 - sigmoid(5(d-3.5))
        float msg = (hadd2(mn2[m]) + b2) * ((hadd2(gt2[m]) + be2v) * cut);
        atomicAdd(&g_msum[srcv[m]*HH + t], msg);
    }
}

// ---------------------------------------------------------------------------
// node update: state += ssp(msum @ Ws1 + bs1) @ Ws2 + bs2 ; write out slab
// ---------------------------------------------------------------------------
__global__ void k_upd(const float* __restrict__ Ws1, const float* __restrict__ bs1,
                      const float* __restrict__ Ws2, const float* __restrict__ bs2,
                      float* __restrict__ out)
{
    __shared__ __align__(16) float As[16][HH];
    __shared__ __align__(16) float Hs[16][HH];
    int t = threadIdx.x;
    int row0 = blockIdx.x*16;
    for (int i = t; i < 16*HH; i += 128)
        As[i>>7][i&127] = g_msum[(row0 + (i>>7))*HH + (i&127)];
    __syncthreads();

    float acc[16];
#pragma unroll
    for (int m = 0; m < 16; m++) acc[m] = 0.0f;
    for (int k = 0; k < HH; k += 4){
        float w0 = Ws1[(k+0)*HH+t], w1 = Ws1[(k+1)*HH+t];
        float w2 = Ws1[(k+2)*HH+t], w3 = Ws1[(k+3)*HH+t];
#pragma unroll
        for (int m = 0; m < 16; m++){
            float4 a = *(const float4*)&As[m][k];
            acc[m] += a.x*w0 + a.y*w1 + a.z*w2 + a.w*w3;
        }
    }
    float b1 = bs1[t];
#pragma unroll
    for (int m = 0; m < 16; m++) Hs[m][t] = sspf(acc[m] + b1);
    __syncthreads();

#pragma unroll
    for (int m = 0; m < 16; m++) acc[m] = 0.0f;
    for (int k = 0; k < HH; k += 4){
        float w0 = Ws2[(k+0)*HH+t], w1 = Ws2[(k+1)*HH+t];
        float w2 = Ws2[(k+2)*HH+t], w3 = Ws2[(k+3)*HH+t];
#pragma unroll
        for (int m = 0; m < 16; m++){
            float4 a = *(const float4*)&Hs[m][k];
            acc[m] += a.x*w0 + a.y*w1 + a.z*w2 + a.w*w3;
        }
    }
    float b2 = bs2[t];
#pragma unroll
    for (int m = 0; m < 16; m++){
        int idx = (row0+m)*HH + t;
        float v = g_state[idx] + acc[m] + b2;
        g_state[idx] = v;
        out[idx] = v;
    }
}

// ---------------------------------------------------------------------------
extern "C" void kernel_launch(void* const* d_in, const int* in_sizes, int n_in,
                              void* d_out, int out_size)
{
    const int*   nodes      = (const int*)  d_in[0];
    const int*   atom_edges = (const int*)  d_in[1];
    const float* feats      = (const float*)d_in[2];
    const int*   num_nodes  = (const int*)  d_in[3];
    // d_in[4] = num_atom_edges (all == EP, unused)
    const float* emb = (const float*)d_in[5];
    const float* Wn1 = (const float*)d_in[6];
    const float* bn1 = (const float*)d_in[7];
    const float* Wn2 = (const float*)d_in[8];
    const float* bn2 = (const float*)d_in[9];
    const float* We1 = (const float*)d_in[10];
    const float* be1 = (const float*)d_in[11];
    const float* We2 = (const float*)d_in[12];
    const float* be2 = (const float*)d_in[13];
    const float* Ws1 = (const float*)d_in[14];
    const float* bs1 = (const float*)d_in[15];
    const float* Ws2 = (const float*)d_in[16];
    const float* bs2 = (const float*)d_in[17];
    float* out = (float*)d_out;

    k_init<<<(NT*HH + 255)/256, 256>>>(nodes, emb, num_nodes);
    for (int l = 0; l < NL; l++){
        k_zero<<<(NT*HH + 255)/256, 256>>>();
        k_pre<<<NT/16, 256>>>(Wn1 + l*2*HH*HH);
        k_edge<<<ET/16, 128>>>(atom_edges, feats,
            bn1 + l*HH, Wn2 + l*HH*HH, bn2 + l*HH,
            We1 + l*ES*HH, be1 + l*HH, We2 + l*HH*HH, be2 + l*HH);
        k_upd<<<NT/16, 128>>>(Ws1 + l*HH*HH, bs1 + l*HH,
                              Ws2 + l*HH*HH, bs2 + l*HH,
                              out + (size_t)l*NT*HH);
    }
}

// round 4
// speedup vs baseline: 1.1381x; 1.1381x over previous
#include <cuda_runtime.h>
#include <math.h>

#define BB 8
#define NP 2048
#define EP 32768
#define NT (BB*NP)      // 16384 total nodes
#define ET (BB*EP)      // 262144 total edges
#define HH 128
#define NL 3
#define ES 50

typedef unsigned long long u64;

// ---- scratch (no allocations allowed; __device__ globals) ----
__device__ float g_state[NT*HH];   // node states
__device__ float g_S[NT*HH];       // state @ Wn1_top  (sender half)
__device__ float g_R[NT*HH];       // state @ Wn1_bot  (receiver half)
__device__ float g_msum[NT*HH];    // per-node message accumulator
__device__ int   g_off[BB];        // exclusive cumsum of num_nodes

__device__ __forceinline__ float sspf(float x){
    // softplus(x) - log(2), numerically stable
    return fmaxf(x, 0.0f) + log1pf(__expf(-fabsf(x))) - 0.69314718055994530942f;
}

// ---- packed f32x2 helpers (sm_100+) ----
__device__ __forceinline__ u64 pk2(float lo, float hi){
    u64 r; asm("mov.b64 %0, {%1, %2};" : "=l"(r) : "f"(lo), "f"(hi)); return r;
}
__device__ __forceinline__ void fma2(u64& d, u64 a, u64 b){
    asm("fma.rn.f32x2 %0, %1, %2, %3;" : "=l"(d) : "l"(a), "l"(b), "l"(d));
}
__device__ __forceinline__ float hadd2(u64 v){
    float lo, hi; asm("mov.b64 {%0, %1}, %2;" : "=f"(lo), "=f"(hi) : "l"(v));
    return lo + hi;
}
__device__ __forceinline__ void barg(int id){
    asm volatile("bar.sync %0, 128;" :: "r"(id) : "memory");
}

// ---------------------------------------------------------------------------
// init: node embedding gather + graph offsets
// ---------------------------------------------------------------------------
__global__ void k_init(const int* __restrict__ nodes, const float* __restrict__ emb,
                       const int* __restrict__ num_nodes){
    int i = blockIdx.x*blockDim.x + threadIdx.x;
    if (i == 0){
        int acc = 0;
        for (int b = 0; b < BB; b++){ g_off[b] = acc; acc += num_nodes[b]; }
    }
    if (i < NT*HH){
        int node = i >> 7, c = i & 127;
        g_state[i] = emb[nodes[node]*HH + c];
    }
}

__global__ void k_zero(){
    int i = blockIdx.x*blockDim.x + threadIdx.x;
    if (i < NT*HH) g_msum[i] = 0.0f;
}

// ---------------------------------------------------------------------------
// node pre-GEMM: S = state @ Wn1[:128], R = state @ Wn1[128:]
// ---------------------------------------------------------------------------
__global__ void k_pre(const float* __restrict__ Wn1){
    __shared__ __align__(16) float As[16][HH];
    int t = threadIdx.x;
    int row0 = blockIdx.x*16;
    for (int i = t; i < 16*HH; i += 256)
        As[i>>7][i&127] = g_state[(row0 + (i>>7))*HH + (i&127)];
    __syncthreads();

    int half = t >> 7;
    int col  = t & 127;
    const float* W = Wn1 + half*HH*HH + col;
    float acc[16];
#pragma unroll
    for (int m = 0; m < 16; m++) acc[m] = 0.0f;
    for (int k = 0; k < HH; k += 4){
        float w0 = W[(k+0)*HH], w1 = W[(k+1)*HH], w2 = W[(k+2)*HH], w3 = W[(k+3)*HH];
#pragma unroll
        for (int m = 0; m < 16; m++){
            float4 a = *(const float4*)&As[m][k];
            acc[m] += a.x*w0 + a.y*w1 + a.z*w2 + a.w*w3;
        }
    }
    float* dst = half ? g_R : g_S;
#pragma unroll
    for (int m = 0; m < 16; m++) dst[(row0+m)*HH + col] = acc[m];
}

// ---------------------------------------------------------------------------
// edge kernel: 16 edges/block, 256 threads, warp-specialized dual path.
//   group A (t<128):  A1 = ssp(S[snd]+R[rcv]+bn1);  mnA = A1@Wn2 + bn2
//   group B (t>=128): es = gauss(d); A2 = ssp(es@We1+be1);
//                     gtB = (A2@We2 + be2) * cut(d)
//   combine: msg = mnA * gtB ; atomicAdd into g_msum[rcv]
// ---------------------------------------------------------------------------
__global__ void __launch_bounds__(256, 4) k_edge(
    const int* __restrict__ atom_edges, const float* __restrict__ feats,
    const float* __restrict__ bn1, const float* __restrict__ Wn2, const float* __restrict__ bn2,
    const float* __restrict__ We1, const float* __restrict__ be1,
    const float* __restrict__ We2, const float* __restrict__ be2)
{
    __shared__ __align__(16) float As1[16][HH];
    __shared__ __align__(16) float As2[16][HH];
    __shared__ __align__(16) float gA[16][HH];
    __shared__ __align__(16) float gB[16][HH];
    __shared__ __align__(16) float es[16][ES];
    __shared__ float sd[16];
    __shared__ int   ssnd[16], srcv[16];

    int t  = threadIdx.x;
    int e0 = blockIdx.x*16;
    if (t < 16){
        int e   = e0 + t;
        int off = g_off[e / EP];
        ssnd[t] = atom_edges[e*2+0] + off;
        srcv[t] = atom_edges[e*2+1] + off;
        sd[t]   = feats[e];
    }
    __syncthreads();

    if (t < 128){
        // ======== group A: node-pair message path ========
        int ta = t;
        float b = bn1[ta];
#pragma unroll
        for (int m = 0; m < 16; m++){
            float v = g_S[ssnd[m]*HH + ta] + g_R[srcv[m]*HH + ta] + b;
            As1[m][ta] = sspf(v);
        }
        barg(1);   // group A: As1 complete

        u64 mn2[16];
#pragma unroll
        for (int m = 0; m < 16; m++) mn2[m] = 0ull;
        for (int k = 0; k < HH; k += 4){
            u64 w1a = pk2(Wn2[(k+0)*HH+ta], Wn2[(k+1)*HH+ta]);
            u64 w1b = pk2(Wn2[(k+2)*HH+ta], Wn2[(k+3)*HH+ta]);
#pragma unroll
            for (int m = 0; m < 16; m++){
                ulonglong2 a1 = *(const ulonglong2*)&As1[m][k];
                fma2(mn2[m], a1.x, w1a);
                fma2(mn2[m], a1.y, w1b);
            }
        }
        float b2 = bn2[ta];
#pragma unroll
        for (int m = 0; m < 16; m++) gA[m][ta] = hadd2(mn2[m]) + b2;
    } else {
        // ======== group B: edge-filter gate path ========
        int tb = t - 128;
        // gaussian radial basis: exp(-(d-mu)^2 / (2*0.1^2))
        for (int i = tb; i < 16*ES; i += 128){
            int m = i / ES, j = i % ES;
            float dd = sd[m] - 0.1f*(float)j;
            es[m][j] = __expf(-dd*dd*50.0f);
        }
        barg(2);   // group B: es complete

        // A2 = ssp(es @ We1 + be1), packed over j pairs
        {
            u64 acc2[16];
#pragma unroll
            for (int m = 0; m < 16; m++) acc2[m] = 0ull;
            for (int j = 0; j < ES; j += 2){
                u64 w = pk2(We1[j*HH + tb], We1[(j+1)*HH + tb]);
#pragma unroll
                for (int m = 0; m < 16; m++){
                    u64 e = *(const u64*)&es[m][j];
                    fma2(acc2[m], e, w);
                }
            }
            float b = be1[tb];
#pragma unroll
            for (int m = 0; m < 16; m++) As2[m][tb] = sspf(hadd2(acc2[m]) + b);
        }
        barg(2);   // group B: As2 complete

        u64 gt2[16];
#pragma unroll
        for (int m = 0; m < 16; m++) gt2[m] = 0ull;
        for (int k = 0; k < HH; k += 4){
            u64 w2a = pk2(We2[(k+0)*HH+tb], We2[(k+1)*HH+tb]);
            u64 w2b = pk2(We2[(k+2)*HH+tb], We2[(k+3)*HH+tb]);
#pragma unroll
            for (int m = 0; m < 16; m++){
                ulonglong2 a2 = *(const ulonglong2*)&As2[m][k];
                fma2(gt2[m], a2.x, w2a);
                fma2(gt2[m], a2.y, w2b);
            }
        }
        float be2v = be2[tb];
#pragma unroll
        for (int m = 0; m < 16; m++){
            float d   = sd[m];
            float cut = 1.0f/(1.0f + __expf(5.0f*(d - 3.5f)));  // 1 - sigmoid(5(d-3.5))
            gB[m][tb] = (hadd2(gt2[m]) + be2v) * cut;
        }
    }
    __syncthreads();

    // combine + scatter: 8 rows per thread-half
    {
        int c  = t & 127;
        int m0 = (t >> 7) * 8;
#pragma unroll
        for (int mm = 0; mm < 8; mm++){
            int m = m0 + mm;
            atomicAdd(&g_msum[srcv[m]*HH + c], gA[m][c] * gB[m][c]);
        }
    }
}

// ---------------------------------------------------------------------------
// node update: state += ssp(msum @ Ws1 + bs1) @ Ws2 + bs2 ; write out slab
// ---------------------------------------------------------------------------
__global__ void k_upd(const float* __restrict__ Ws1, const float* __restrict__ bs1,
                      const float* __restrict__ Ws2, const float* __restrict__ bs2,
                      float* __restrict__ out)
{
    __shared__ __align__(16) float As[16][HH];
    __shared__ __align__(16) float Hs[16][HH];
    int t = threadIdx.x;
    int row0 = blockIdx.x*16;
    for (int i = t; i < 16*HH; i += 128)
        As[i>>7][i&127] = g_msum[(row0 + (i>>7))*HH + (i&127)];
    __syncthreads();

    float acc[16];
#pragma unroll
    for (int m = 0; m < 16; m++) acc[m] = 0.0f;
    for (int k = 0; k < HH; k += 4){
        float w0 = Ws1[(k+0)*HH+t], w1 = Ws1[(k+1)*HH+t];
        float w2 = Ws1[(k+2)*HH+t], w3 = Ws1[(k+3)*HH+t];
#pragma unroll
        for (int m = 0; m < 16; m++){
            float4 a = *(const float4*)&As[m][k];
            acc[m] += a.x*w0 + a.y*w1 + a.z*w2 + a.w*w3;
        }
    }
    float b1 = bs1[t];
#pragma unroll
    for (int m = 0; m < 16; m++) Hs[m][t] = sspf(acc[m] + b1);
    __syncthreads();

#pragma unroll
    for (int m = 0; m < 16; m++) acc[m] = 0.0f;
    for (int k = 0; k < HH; k += 4){
        float w0 = Ws2[(k+0)*HH+t], w1 = Ws2[(k+1)*HH+t];
        float w2 = Ws2[(k+2)*HH+t], w3 = Ws2[(k+3)*HH+t];
#pragma unroll
        for (int m = 0; m < 16; m++){
            float4 a = *(const float4*)&Hs[m][k];
            acc[m] += a.x*w0 + a.y*w1 + a.z*w2 + a.w*w3;
        }
    }
    float b2 = bs2[t];
#pragma unroll
    for (int m = 0; m < 16; m++){
        int idx = (row0+m)*HH + t;
        float v = g_state[idx] + acc[m] + b2;
        g_state[idx] = v;
        out[idx] = v;
    }
}

// ---------------------------------------------------------------------------
extern "C" void kernel_launch(void* const* d_in, const int* in_sizes, int n_in,
                              void* d_out, int out_size)
{
    const int*   nodes      = (const int*)  d_in[0];
    const int*   atom_edges = (const int*)  d_in[1];
    const float* feats      = (const float*)d_in[2];
    const int*   num_nodes  = (const int*)  d_in[3];
    // d_in[4] = num_atom_edges (all == EP, unused)
    const float* emb = (const float*)d_in[5];
    const float* Wn1 = (const float*)d_in[6];
    const float* bn1 = (const float*)d_in[7];
    const float* Wn2 = (const float*)d_in[8];
    const float* bn2 = (const float*)d_in[9];
    const float* We1 = (const float*)d_in[10];
    const float* be1 = (const float*)d_in[11];
    const float* We2 = (const float*)d_in[12];
    const float* be2 = (const float*)d_in[13];
    const float* Ws1 = (const float*)d_in[14];
    const float* bs1 = (const float*)d_in[15];
    const float* Ws2 = (const float*)d_in[16];
    const float* bs2 = (const float*)d_in[17];
    float* out = (float*)d_out;

    k_init<<<(NT*HH + 255)/256, 256>>>(nodes, emb, num_nodes);
    for (int l = 0; l < NL; l++){
        k_zero<<<(NT*HH + 255)/256, 256>>>();
        k_pre<<<NT/16, 256>>>(Wn1 + l*2*HH*HH);
        k_edge<<<ET/16, 256>>>(atom_edges, feats,
            bn1 + l*HH, Wn2 + l*HH*HH, bn2 + l*HH,
            We1 + l*ES*HH, be1 + l*HH, We2 + l*HH*HH, be2 + l*HH);
        k_upd<<<NT/16, 128>>>(Ws1 + l*HH*HH, bs1 + l*HH,
                              Ws2 + l*HH*HH, bs2 + l*HH,
                              out + (size_t)l*NT*HH);
    }
}

// round 5
// speedup vs baseline: 1.4728x; 1.2941x over previous
#include <cuda_runtime.h>
#include <math.h>

#define BB 8
#define NP 2048
#define EP 32768
#define NT (BB*NP)      // 16384 total nodes
#define ET (BB*EP)      // 262144 total edges
#define HH 128
#define NL 3
#define ES 50

// ---- edge-kernel tiling ----
#define MT 32                   // edges per tile
#define NTILES (ET/MT)          // 8192
#define GRID_EDGE 148           // persistent blocks (1/SM)

// smem layout (float indices); strides padded for conflict-free mma frag loads
#define SA  132                 // activation row stride (A1/A2)
#define SE  60                  // es row stride
#define SWW 136                 // weight row stride
#define OFF_A1  0
#define OFF_A2  (OFF_A1 + MT*SA)        // 4224
#define OFF_ES  (OFF_A2 + MT*SA)        // 8448
#define OFF_W1  (OFF_ES + MT*SE)        // 10368 (56 rows: We1 padded)
#define OFF_W2  (OFF_W1 + 56*SWW)       // 17984 (Wn2)
#define OFF_W3  (OFF_W2 + HH*SWW)       // 35392 (We2)
#define OFF_BN1 (OFF_W3 + HH*SWW)       // 52800
#define OFF_SD  (OFF_BN1 + HH)
#define OFF_CUT (OFF_SD + MT)
#define OFF_SND (OFF_CUT + MT)
#define OFF_RCV (OFF_SND + MT)
#define SMEM_FLOATS (OFF_RCV + MT)      // 53056 floats = 212224 B

// ---- scratch (no allocations allowed; __device__ globals) ----
__device__ float g_state[NT*HH];
__device__ float g_S[NT*HH];
__device__ float g_R[NT*HH];
__device__ float g_msum[NT*HH];
__device__ int   g_off[BB];

__device__ __forceinline__ float sspf(float x){
    return fmaxf(x, 0.0f) + log1pf(__expf(-fabsf(x))) - 0.69314718055994530942f;
}
__device__ __forceinline__ unsigned tf32c(float f){
    unsigned r; asm("cvt.rna.tf32.f32 %0, %1;" : "=r"(r) : "f"(f)); return r;
}
__device__ __forceinline__ void mma8(float* d, const unsigned* a, const unsigned* b){
    asm volatile("mma.sync.aligned.m16n8k8.row.col.f32.tf32.tf32.f32 "
        "{%0,%1,%2,%3},{%4,%5,%6,%7},{%8,%9},{%0,%1,%2,%3};"
        : "+f"(d[0]),"+f"(d[1]),"+f"(d[2]),"+f"(d[3])
        : "r"(a[0]),"r"(a[1]),"r"(a[2]),"r"(a[3]),"r"(b[0]),"r"(b[1]));
}

// ---------------------------------------------------------------------------
__global__ void k_init(const int* __restrict__ nodes, const float* __restrict__ emb,
                       const int* __restrict__ num_nodes){
    int i = blockIdx.x*blockDim.x + threadIdx.x;
    if (i == 0){
        int acc = 0;
        for (int b = 0; b < BB; b++){ g_off[b] = acc; acc += num_nodes[b]; }
    }
    if (i < NT*HH){
        int node = i >> 7, c = i & 127;
        g_state[i] = emb[nodes[node]*HH + c];
    }
}

__global__ void k_zero(){
    int i = blockIdx.x*blockDim.x + threadIdx.x;
    if (i < NT*HH) g_msum[i] = 0.0f;
}

// ---------------------------------------------------------------------------
// node pre-GEMM: S = state @ Wn1[:128], R = state @ Wn1[128:]
// ---------------------------------------------------------------------------
__global__ void k_pre(const float* __restrict__ Wn1){
    __shared__ __align__(16) float As[16][HH];
    int t = threadIdx.x;
    int row0 = blockIdx.x*16;
    for (int i = t; i < 16*HH; i += 256)
        As[i>>7][i&127] = g_state[(row0 + (i>>7))*HH + (i&127)];
    __syncthreads();

    int half = t >> 7;
    int col  = t & 127;
    const float* W = Wn1 + half*HH*HH + col;
    float acc[16];
#pragma unroll
    for (int m = 0; m < 16; m++) acc[m] = 0.0f;
    for (int k = 0; k < HH; k += 4){
        float w0 = W[(k+0)*HH], w1 = W[(k+1)*HH], w2 = W[(k+2)*HH], w3 = W[(k+3)*HH];
#pragma unroll
        for (int m = 0; m < 16; m++){
            float4 a = *(const float4*)&As[m][k];
            acc[m] += a.x*w0 + a.y*w1 + a.z*w2 + a.w*w3;
        }
    }
    float* dst = half ? g_R : g_S;
#pragma unroll
    for (int m = 0; m < 16; m++) dst[(row0+m)*HH + col] = acc[m];
}

// ---------------------------------------------------------------------------
// persistent tensor-core edge kernel (tf32 mma.sync)
//   per 32-edge tile:
//     A1 = ssp(S[snd]+R[rcv]+bn1)                   [32,128]
//     A2 = ssp(gauss(d) @ We1 + be1)                [32,128]  (GEMM1, K=56 padded)
//     mn = A1 @ Wn2                                 (GEMM2)
//     gt = A2 @ We2                                 (GEMM3)
//     msg = (mn+bn2) * ((gt+be2)*cut) ; atomicAdd into g_msum[rcv]
//   Weights staged in smem ONCE per block (persistent over ~55 tiles).
// ---------------------------------------------------------------------------
__global__ void __launch_bounds__(256) k_edge(
    const int* __restrict__ atom_edges, const float* __restrict__ feats,
    const float* __restrict__ bn1, const float* __restrict__ Wn2, const float* __restrict__ bn2,
    const float* __restrict__ We1, const float* __restrict__ be1,
    const float* __restrict__ We2, const float* __restrict__ be2)
{
    extern __shared__ float sm[];
    unsigned* smu = (unsigned*)sm;
    int*      smi = (int*)sm;

    int t = threadIdx.x, lane = t & 31, w = t >> 5;
    int g = lane >> 2, tid = lane & 3;

    // ---- stage weights (tf32), biases ----
    for (int i = t; i < 56*HH; i += 256){
        int r = i >> 7, c = i & 127;
        float v = (r < ES) ? We1[r*HH + c] : 0.0f;
        smu[OFF_W1 + r*SWW + c] = tf32c(v);
    }
    for (int i = t; i < HH*HH; i += 256){
        int r = i >> 7, c = i & 127;
        smu[OFF_W2 + r*SWW + c] = tf32c(Wn2[i]);
        smu[OFF_W3 + r*SWW + c] = tf32c(We2[i]);
    }
    if (t < HH) sm[OFF_BN1 + t] = bn1[t];

    // ---- per-thread tile coordinates & column constants ----
    int mt = w & 1;            // mtile: rows mt*16 + g, +8
    int nq = w >> 1;           // 4 ntiles: (nq*4+ntl)*8
    int r0 = mt*16 + g, r1 = r0 + 8;
    float bn2r[8], be2r[8], be1r[8];
    int ncol0[4];
#pragma unroll
    for (int ntl = 0; ntl < 4; ntl++){
        int c0 = (nq*4 + ntl)*8 + 2*tid;
        ncol0[ntl] = c0;
        bn2r[2*ntl] = bn2[c0]; bn2r[2*ntl+1] = bn2[c0+1];
        be2r[2*ntl] = be2[c0]; be2r[2*ntl+1] = be2[c0+1];
        be1r[2*ntl] = be1[c0]; be1r[2*ntl+1] = be1[c0+1];
    }
    __syncthreads();

    for (int tile = blockIdx.x; tile < NTILES; tile += gridDim.x){
        __syncthreads();   // previous tile fully done before overwriting smem
        if (t < MT){
            int e   = tile*MT + t;
            int off = g_off[e / EP];
            smi[OFF_SND + t] = atom_edges[e*2+0] + off;
            smi[OFF_RCV + t] = atom_edges[e*2+1] + off;
            float d = feats[e];
            sm[OFF_SD + t]  = d;
            sm[OFF_CUT + t] = 1.0f/(1.0f + __expf(5.0f*(d - 3.5f)));
        }
        __syncthreads();

        // es (padded K to 56) and A1 fills
        for (int i = t; i < MT*56; i += 256){
            int m = i / 56, j = i - m*56;
            float d  = sm[OFF_SD + m];
            float dd = d - 0.1f*(float)j;
            float v  = (j < ES) ? __expf(-dd*dd*50.0f) : 0.0f;
            smu[OFF_ES + m*SE + j] = tf32c(v);
        }
        for (int i = t; i < MT*HH; i += 256){
            int m = i >> 7, c = i & 127;
            int sn = smi[OFF_SND + m], rc = smi[OFF_RCV + m];
            float v = g_S[sn*HH + c] + g_R[rc*HH + c] + sm[OFF_BN1 + c];
            smu[OFF_A1 + m*SA + c] = tf32c(sspf(v));
        }
        __syncthreads();

        // ---- GEMM1: es @ We1 (+be1, ssp) -> A2 ----
        {
            float d1[4][4];
#pragma unroll
            for (int i = 0; i < 4; i++)
#pragma unroll
                for (int j = 0; j < 4; j++) d1[i][j] = 0.0f;
#pragma unroll
            for (int kt = 0; kt < 7; kt++){
                int k0 = kt*8;
                unsigned a[4];
                a[0] = smu[OFF_ES + r0*SE + k0 + tid];
                a[1] = smu[OFF_ES + r1*SE + k0 + tid];
                a[2] = smu[OFF_ES + r0*SE + k0 + tid + 4];
                a[3] = smu[OFF_ES + r1*SE + k0 + tid + 4];
#pragma unroll
                for (int ntl = 0; ntl < 4; ntl++){
                    int nb = (nq*4 + ntl)*8 + g;
                    unsigned b[2];
                    b[0] = smu[OFF_W1 + (k0+tid)*SWW + nb];
                    b[1] = smu[OFF_W1 + (k0+tid+4)*SWW + nb];
                    mma8(d1[ntl], a, b);
                }
            }
#pragma unroll
            for (int ntl = 0; ntl < 4; ntl++){
                int c0 = ncol0[ntl];
                smu[OFF_A2 + r0*SA + c0  ] = tf32c(sspf(d1[ntl][0] + be1r[2*ntl]));
                smu[OFF_A2 + r0*SA + c0+1] = tf32c(sspf(d1[ntl][1] + be1r[2*ntl+1]));
                smu[OFF_A2 + r1*SA + c0  ] = tf32c(sspf(d1[ntl][2] + be1r[2*ntl]));
                smu[OFF_A2 + r1*SA + c0+1] = tf32c(sspf(d1[ntl][3] + be1r[2*ntl+1]));
            }
        }
        __syncthreads();

        // ---- GEMM2: mn = A1 @ Wn2 ; GEMM3: gt = A2 @ We2 ----
        float dm[4][4], dg[4][4];
#pragma unroll
        for (int i = 0; i < 4; i++)
#pragma unroll
            for (int j = 0; j < 4; j++){ dm[i][j] = 0.0f; dg[i][j] = 0.0f; }

#pragma unroll
        for (int kt = 0; kt < 16; kt++){
            int k0 = kt*8;
            unsigned a[4];
            a[0] = smu[OFF_A1 + r0*SA + k0 + tid];
            a[1] = smu[OFF_A1 + r1*SA + k0 + tid];
            a[2] = smu[OFF_A1 + r0*SA + k0 + tid + 4];
            a[3] = smu[OFF_A1 + r1*SA + k0 + tid + 4];
#pragma unroll
            for (int ntl = 0; ntl < 4; ntl++){
                int nb = (nq*4 + ntl)*8 + g;
                unsigned b[2];
                b[0] = smu[OFF_W2 + (k0+tid)*SWW + nb];
                b[1] = smu[OFF_W2 + (k0+tid+4)*SWW + nb];
                mma8(dm[ntl], a, b);
            }
        }
#pragma unroll
        for (int kt = 0; kt < 16; kt++){
            int k0 = kt*8;
            unsigned a[4];
            a[0] = smu[OFF_A2 + r0*SA + k0 + tid];
            a[1] = smu[OFF_A2 + r1*SA + k0 + tid];
            a[2] = smu[OFF_A2 + r0*SA + k0 + tid + 4];
            a[3] = smu[OFF_A2 + r1*SA + k0 + tid + 4];
#pragma unroll
            for (int ntl = 0; ntl < 4; ntl++){
                int nb = (nq*4 + ntl)*8 + g;
                unsigned b[2];
                b[0] = smu[OFF_W3 + (k0+tid)*SWW + nb];
                b[1] = smu[OFF_W3 + (k0+tid+4)*SWW + nb];
                mma8(dg[ntl], a, b);
            }
        }

        // ---- combine + scatter ----
        float cut0 = sm[OFF_CUT + r0], cut1 = sm[OFF_CUT + r1];
        int rcv0 = smi[OFF_RCV + r0], rcv1 = smi[OFF_RCV + r1];
#pragma unroll
        for (int ntl = 0; ntl < 4; ntl++){
            int c0 = ncol0[ntl];
            float m00 = (dm[ntl][0] + bn2r[2*ntl  ]) * ((dg[ntl][0] + be2r[2*ntl  ]) * cut0);
            float m01 = (dm[ntl][1] + bn2r[2*ntl+1]) * ((dg[ntl][1] + be2r[2*ntl+1]) * cut0);
            float m10 = (dm[ntl][2] + bn2r[2*ntl  ]) * ((dg[ntl][2] + be2r[2*ntl  ]) * cut1);
            float m11 = (dm[ntl][3] + bn2r[2*ntl+1]) * ((dg[ntl][3] + be2r[2*ntl+1]) * cut1);
            atomicAdd(&g_msum[rcv0*HH + c0  ], m00);
            atomicAdd(&g_msum[rcv0*HH + c0+1], m01);
            atomicAdd(&g_msum[rcv1*HH + c0  ], m10);
            atomicAdd(&g_msum[rcv1*HH + c0+1], m11);
        }
    }
}

// ---------------------------------------------------------------------------
// node update: state += ssp(msum @ Ws1 + bs1) @ Ws2 + bs2 ; write out slab
// ---------------------------------------------------------------------------
__global__ void k_upd(const float* __restrict__ Ws1, const float* __restrict__ bs1,
                      const float* __restrict__ Ws2, const float* __restrict__ bs2,
                      float* __restrict__ out)
{
    __shared__ __align__(16) float As[16][HH];
    __shared__ __align__(16) float Hs[16][HH];
    int t = threadIdx.x;
    int row0 = blockIdx.x*16;
    for (int i = t; i < 16*HH; i += 128)
        As[i>>7][i&127] = g_msum[(row0 + (i>>7))*HH + (i&127)];
    __syncthreads();

    float acc[16];
#pragma unroll
    for (int m = 0; m < 16; m++) acc[m] = 0.0f;
    for (int k = 0; k < HH; k += 4){
        float w0 = Ws1[(k+0)*HH+t], w1 = Ws1[(k+1)*HH+t];
        float w2 = Ws1[(k+2)*HH+t], w3 = Ws1[(k+3)*HH+t];
#pragma unroll
        for (int m = 0; m < 16; m++){
            float4 a = *(const float4*)&As[m][k];
            acc[m] += a.x*w0 + a.y*w1 + a.z*w2 + a.w*w3;
        }
    }
    float b1 = bs1[t];
#pragma unroll
    for (int m = 0; m < 16; m++) Hs[m][t] = sspf(acc[m] + b1);
    __syncthreads();

#pragma unroll
    for (int m = 0; m < 16; m++) acc[m] = 0.0f;
    for (int k = 0; k < HH; k += 4){
        float w0 = Ws2[(k+0)*HH+t], w1 = Ws2[(k+1)*HH+t];
        float w2 = Ws2[(k+2)*HH+t], w3 = Ws2[(k+3)*HH+t];
#pragma unroll
        for (int m = 0; m < 16; m++){
            float4 a = *(const float4*)&Hs[m][k];
            acc[m] += a.x*w0 + a.y*w1 + a.z*w2 + a.w*w3;
        }
    }
    float b2 = bs2[t];
#pragma unroll
    for (int m = 0; m < 16; m++){
        int idx = (row0+m)*HH + t;
        float v = g_state[idx] + acc[m] + b2;
        g_state[idx] = v;
        out[idx] = v;
    }
}

// ---------------------------------------------------------------------------
extern "C" void kernel_launch(void* const* d_in, const int* in_sizes, int n_in,
                              void* d_out, int out_size)
{
    const int*   nodes      = (const int*)  d_in[0];
    const int*   atom_edges = (const int*)  d_in[1];
    const float* feats      = (const float*)d_in[2];
    const int*   num_nodes  = (const int*)  d_in[3];
    // d_in[4] = num_atom_edges (all == EP, unused)
    const float* emb = (const float*)d_in[5];
    const float* Wn1 = (const float*)d_in[6];
    const float* bn1 = (const float*)d_in[7];
    const float* Wn2 = (const float*)d_in[8];
    const float* bn2 = (const float*)d_in[9];
    const float* We1 = (const float*)d_in[10];
    const float* be1 = (const float*)d_in[11];
    const float* We2 = (const float*)d_in[12];
    const float* be2 = (const float*)d_in[13];
    const float* Ws1 = (const float*)d_in[14];
    const float* bs1 = (const float*)d_in[15];
    const float* Ws2 = (const float*)d_in[16];
    const float* bs2 = (const float*)d_in[17];
    float* out = (float*)d_out;

    cudaFuncSetAttribute(k_edge, cudaFuncAttributeMaxDynamicSharedMemorySize,
                         SMEM_FLOATS*sizeof(float));

    k_init<<<(NT*HH + 255)/256, 256>>>(nodes, emb, num_nodes);
    for (int l = 0; l < NL; l++){
        k_zero<<<(NT*HH + 255)/256, 256>>>();
        k_pre<<<NT/16, 256>>>(Wn1 + l*2*HH*HH);
        k_edge<<<GRID_EDGE, 256, SMEM_FLOATS*sizeof(float)>>>(atom_edges, feats,
            bn1 + l*HH, Wn2 + l*HH*HH, bn2 + l*HH,
            We1 + l*ES*HH, be1 + l*HH, We2 + l*HH*HH, be2 + l*HH);
        k_upd<<<NT/16, 128>>>(Ws1 + l*HH*HH, bs1 + l*HH,
                              Ws2 + l*HH*HH, bs2 + l*HH,
                              out + (size_t)l*NT*HH);
    }
}

// round 6
// speedup vs baseline: 3.1244x; 2.1213x over previous
#include <cuda_runtime.h>
#include <math.h>

#define BB 8
#define NP 2048
#define EP 32768
#define NT (BB*NP)      // 16384 total nodes
#define ET (BB*EP)      // 262144 total edges
#define HH 128
#define NL 3
#define ES 50

// ---- edge-kernel tiling ----
#define MT 32                   // edges per tile
#define NTILES (ET/MT)          // 8192
#define GRID_EDGE 296           // 2 blocks/SM

// smem layout in 32-bit WORDS (each word = bf16x2 = 2 k-consecutive elems)
// strides chosen so (stride*g) % 32 == 8g -> conflict-free mma frag access
#define A1S 72                  // A1 row stride (words); 64 cols -> 64 words used
#define A2S 72
#define W1S 40                  // W1^T row stride (words); K=64 bf16 -> 32 words
#define W2S 72                  // W2^T/W3^T: K=128 bf16 -> 64 words
#define OFF_A1 0
#define OFF_A2 (OFF_A1 + MT*A1S)        // 2304
#define OFF_W1 (OFF_A2 + MT*A2S)        // 4608
#define OFF_W2 (OFF_W1 + HH*W1S)        // 9728
#define OFF_W3 (OFF_W2 + HH*W2S)        // 18944
#define SMEM_WORDS (OFF_W3 + HH*W2S)    // 28160 words = 112640 B

// ---- scratch (no allocations allowed; __device__ globals) ----
__device__ float g_state[NT*HH];
__device__ float g_S[NT*HH];
__device__ float g_R[NT*HH];
__device__ float g_msum[NT*HH];
__device__ int   g_off[BB];

__device__ __forceinline__ float sspf(float x){
    // softplus(x) - log2, fast path (__logf instead of log1pf; abs err ~1e-7)
    return fmaxf(x, 0.0f) + __logf(1.0f + __expf(-fabsf(x))) - 0.69314718055994530942f;
}
__device__ __forceinline__ unsigned bf2(float lo, float hi){
    unsigned r; asm("cvt.rn.bf16x2.f32 %0, %1, %2;" : "=r"(r) : "f"(hi), "f"(lo)); return r;
}
__device__ __forceinline__ void mma16(float* d, unsigned a0, unsigned a1, unsigned a2,
                                      unsigned a3, unsigned b0, unsigned b1){
    asm volatile("mma.sync.aligned.m16n8k16.row.col.f32.bf16.bf16.f32 "
        "{%0,%1,%2,%3},{%4,%5,%6,%7},{%8,%9},{%0,%1,%2,%3};"
        : "+f"(d[0]),"+f"(d[1]),"+f"(d[2]),"+f"(d[3])
        : "r"(a0),"r"(a1),"r"(a2),"r"(a3),"r"(b0),"r"(b1));
}
__device__ __forceinline__ float gsf(float d, int j){
    // gaussian radial basis, zero-padded past ES
    if (j >= ES) return 0.0f;
    float dd = d - 0.1f*(float)j;
    return __expf(-dd*dd*50.0f);
}

// ---------------------------------------------------------------------------
__global__ void k_init(const int* __restrict__ nodes, const float* __restrict__ emb,
                       const int* __restrict__ num_nodes){
    int i = blockIdx.x*blockDim.x + threadIdx.x;
    if (i == 0){
        int acc = 0;
        for (int b = 0; b < BB; b++){ g_off[b] = acc; acc += num_nodes[b]; }
    }
    if (i < NT*HH){
        int node = i >> 7, c = i & 127;
        g_state[i] = emb[nodes[node]*HH + c];
    }
}

__global__ void k_zero(){
    int i = blockIdx.x*blockDim.x + threadIdx.x;
    if (i < NT*HH) g_msum[i] = 0.0f;
}

// ---------------------------------------------------------------------------
// node pre-GEMM: S = state @ Wn1[:128], R = state @ Wn1[128:]
// ---------------------------------------------------------------------------
__global__ void k_pre(const float* __restrict__ Wn1){
    __shared__ __align__(16) float As[16][HH];
    int t = threadIdx.x;
    int row0 = blockIdx.x*16;
    for (int i = t; i < 16*HH; i += 256)
        As[i>>7][i&127] = g_state[(row0 + (i>>7))*HH + (i&127)];
    __syncthreads();

    int half = t >> 7;
    int col  = t & 127;
    const float* W = Wn1 + half*HH*HH + col;
    float acc[16];
#pragma unroll
    for (int m = 0; m < 16; m++) acc[m] = 0.0f;
    for (int k = 0; k < HH; k += 4){
        float w0 = W[(k+0)*HH], w1 = W[(k+1)*HH], w2 = W[(k+2)*HH], w3 = W[(k+3)*HH];
#pragma unroll
        for (int m = 0; m < 16; m++){
            float4 a = *(const float4*)&As[m][k];
            acc[m] += a.x*w0 + a.y*w1 + a.z*w2 + a.w*w3;
        }
    }
    float* dst = half ? g_R : g_S;
#pragma unroll
    for (int m = 0; m < 16; m++) dst[(row0+m)*HH + col] = acc[m];
}

// ---------------------------------------------------------------------------
// persistent bf16 tensor-core edge kernel.  256 threads, 2 blocks/SM.
// 8 warps: mt = w&1 (rows mt*16+g, +8), nq = w>>1 (cols nq*32 .. +31, 4 ntl)
// per 32-edge tile (2 barriers):
//   phase1: issue S/R gather LDGs; GEMM1 es(regs)@We1^T -> A2(bf16 smem);
//           A1 = ssp(gather + bn1) -> bf16 smem
//   phase2: GEMM2 A1@Wn2^T, GEMM3 A2@We2^T; combine; atomicAdd scatter
// ---------------------------------------------------------------------------
__global__ void __launch_bounds__(256, 2) k_edge(
    const int* __restrict__ atom_edges, const float* __restrict__ feats,
    const float* __restrict__ bn1, const float* __restrict__ Wn2, const float* __restrict__ bn2,
    const float* __restrict__ We1, const float* __restrict__ be1,
    const float* __restrict__ We2, const float* __restrict__ be2)
{
    extern __shared__ unsigned smw[];
    int t = threadIdx.x, lane = t & 31, w = t >> 5;
    int g = lane >> 2, tid = lane & 3;

    // ---- stage weights transposed as bf16x2 words: Wt[n][kw] ----
    for (int i = t; i < HH*32; i += 256){          // We1: K=50 padded to 64
        int n = i & 127, kw = i >> 7, k = 2*kw;
        float lo = (k   < ES) ? We1[(k  )*HH + n] : 0.0f;
        float hi = (k+1 < ES) ? We1[(k+1)*HH + n] : 0.0f;
        smw[OFF_W1 + n*W1S + kw] = bf2(lo, hi);
    }
    for (int i = t; i < HH*64; i += 256){
        int n = i & 127, kw = i >> 7, k = 2*kw;
        smw[OFF_W2 + n*W2S + kw] = bf2(Wn2[k*HH + n], Wn2[(k+1)*HH + n]);
        smw[OFF_W3 + n*W2S + kw] = bf2(We2[k*HH + n], We2[(k+1)*HH + n]);
    }

    // ---- per-thread coords ----
    int mt = w & 1, nq = w >> 1;
    int r0 = mt*16 + g, r1 = r0 + 8;
    int fc = (t & 63)*2;       // fill column pair
    int fr = t >> 6;           // fill row base (0..3)
    float bn1a = bn1[fc], bn1b = bn1[fc+1];

    for (int tile = blockIdx.x; tile < NTILES; tile += gridDim.x){
        __syncthreads();   // prev tile's smem reads complete; weights staged (1st iter)
        int e0t = tile*MT;
        int off = g_off[tile >> 10];

        // ---- issue gather loads for A1 (latency hidden under GEMM1) ----
        float2 sv[8], rv[8];
#pragma unroll
        for (int j = 0; j < 8; j++){
            int e  = e0t + fr + 4*j;
            int sn = atom_edges[2*e]   + off;
            int rc = atom_edges[2*e+1] + off;
            sv[j] = *(const float2*)&g_S[sn*HH + fc];
            rv[j] = *(const float2*)&g_R[rc*HH + fc];
        }

        // ---- GEMM1: es (computed in regs) @ We1^T -> A2 ----
        float dr0f = feats[e0t + r0], dr1f = feats[e0t + r1];
        float d1[4][4];
#pragma unroll
        for (int i = 0; i < 4; i++)
#pragma unroll
            for (int j = 0; j < 4; j++) d1[i][j] = 0.0f;
#pragma unroll
        for (int kt = 0; kt < 4; kt++){
            int k0 = kt*16;
            unsigned a0 = bf2(gsf(dr0f, k0+2*tid  ), gsf(dr0f, k0+2*tid+1));
            unsigned a1 = bf2(gsf(dr1f, k0+2*tid  ), gsf(dr1f, k0+2*tid+1));
            unsigned a2 = bf2(gsf(dr0f, k0+2*tid+8), gsf(dr0f, k0+2*tid+9));
            unsigned a3 = bf2(gsf(dr1f, k0+2*tid+8), gsf(dr1f, k0+2*tid+9));
#pragma unroll
            for (int ntl = 0; ntl < 4; ntl++){
                int n = nq*32 + ntl*8 + g;
                unsigned b0 = smw[OFF_W1 + n*W1S + kt*8 + tid];
                unsigned b1 = smw[OFF_W1 + n*W1S + kt*8 + tid + 4];
                mma16(d1[ntl], a0, a1, a2, a3, b0, b1);
            }
        }
        // write A2 = bf16(ssp(d1 + be1))
#pragma unroll
        for (int ntl = 0; ntl < 4; ntl++){
            int c0 = nq*32 + ntl*8 + 2*tid;
            float e1 = be1[c0], e2 = be1[c0+1];
            int cw = c0 >> 1;
            smw[OFF_A2 + r0*A2S + cw] = bf2(sspf(d1[ntl][0]+e1), sspf(d1[ntl][1]+e2));
            smw[OFF_A2 + r1*A2S + cw] = bf2(sspf(d1[ntl][2]+e1), sspf(d1[ntl][3]+e2));
        }
        // write A1 = bf16(ssp(S+R+bn1))
#pragma unroll
        for (int j = 0; j < 8; j++){
            int m = fr + 4*j;
            smw[OFF_A1 + m*A1S + (t & 63)] =
                bf2(sspf(sv[j].x + rv[j].x + bn1a), sspf(sv[j].y + rv[j].y + bn1b));
        }
        __syncthreads();

        // ---- GEMM2: mn = A1 @ Wn2^T ; GEMM3: gt = A2 @ We2^T ----
        float dm[4][4], dg[4][4];
#pragma unroll
        for (int i = 0; i < 4; i++)
#pragma unroll
            for (int j = 0; j < 4; j++){ dm[i][j] = 0.0f; dg[i][j] = 0.0f; }

#pragma unroll
        for (int kt = 0; kt < 8; kt++){
            unsigned a0 = smw[OFF_A1 + r0*A1S + kt*8 + tid];
            unsigned a1 = smw[OFF_A1 + r1*A1S + kt*8 + tid];
            unsigned a2 = smw[OFF_A1 + r0*A1S + kt*8 + tid + 4];
            unsigned a3 = smw[OFF_A1 + r1*A1S + kt*8 + tid + 4];
#pragma unroll
            for (int ntl = 0; ntl < 4; ntl++){
                int n = nq*32 + ntl*8 + g;
                unsigned b0 = smw[OFF_W2 + n*W2S + kt*8 + tid];
                unsigned b1 = smw[OFF_W2 + n*W2S + kt*8 + tid + 4];
                mma16(dm[ntl], a0, a1, a2, a3, b0, b1);
            }
        }
#pragma unroll
        for (int kt = 0; kt < 8; kt++){
            unsigned a0 = smw[OFF_A2 + r0*A2S + kt*8 + tid];
            unsigned a1 = smw[OFF_A2 + r1*A2S + kt*8 + tid];
            unsigned a2 = smw[OFF_A2 + r0*A2S + kt*8 + tid + 4];
            unsigned a3 = smw[OFF_A2 + r1*A2S + kt*8 + tid + 4];
#pragma unroll
            for (int ntl = 0; ntl < 4; ntl++){
                int n = nq*32 + ntl*8 + g;
                unsigned b0 = smw[OFF_W3 + n*W2S + kt*8 + tid];
                unsigned b1 = smw[OFF_W3 + n*W2S + kt*8 + tid + 4];
                mma16(dg[ntl], a0, a1, a2, a3, b0, b1);
            }
        }

        // ---- combine + scatter ----
        float cut0 = 1.0f/(1.0f + __expf(5.0f*(dr0f - 3.5f)));
        float cut1 = 1.0f/(1.0f + __expf(5.0f*(dr1f - 3.5f)));
        int rcv0 = atom_edges[2*(e0t + r0) + 1] + off;
        int rcv1 = atom_edges[2*(e0t + r1) + 1] + off;
#pragma unroll
        for (int ntl = 0; ntl < 4; ntl++){
            int c0 = nq*32 + ntl*8 + 2*tid;
            float n0 = bn2[c0], n1 = bn2[c0+1];
            float q0 = be2[c0], q1 = be2[c0+1];
            atomicAdd(&g_msum[rcv0*HH + c0  ], (dm[ntl][0]+n0) * ((dg[ntl][0]+q0)*cut0));
            atomicAdd(&g_msum[rcv0*HH + c0+1], (dm[ntl][1]+n1) * ((dg[ntl][1]+q1)*cut0));
            atomicAdd(&g_msum[rcv1*HH + c0  ], (dm[ntl][2]+n0) * ((dg[ntl][2]+q0)*cut1));
            atomicAdd(&g_msum[rcv1*HH + c0+1], (dm[ntl][3]+n1) * ((dg[ntl][3]+q1)*cut1));
        }
    }
}

// ---------------------------------------------------------------------------
// node update: state += ssp(msum @ Ws1 + bs1) @ Ws2 + bs2 ; write out slab
// ---------------------------------------------------------------------------
__global__ void k_upd(const float* __restrict__ Ws1, const float* __restrict__ bs1,
                      const float* __restrict__ Ws2, const float* __restrict__ bs2,
                      float* __restrict__ out)
{
    __shared__ __align__(16) float As[16][HH];
    __shared__ __align__(16) float Hs[16][HH];
    int t = threadIdx.x;
    int row0 = blockIdx.x*16;
    for (int i = t; i < 16*HH; i += 128)
        As[i>>7][i&127] = g_msum[(row0 + (i>>7))*HH + (i&127)];
    __syncthreads();

    float acc[16];
#pragma unroll
    for (int m = 0; m < 16; m++) acc[m] = 0.0f;
    for (int k = 0; k < HH; k += 4){
        float w0 = Ws1[(k+0)*HH+t], w1 = Ws1[(k+1)*HH+t];
        float w2 = Ws1[(k+2)*HH+t], w3 = Ws1[(k+3)*HH+t];
#pragma unroll
        for (int m = 0; m < 16; m++){
            float4 a = *(const float4*)&As[m][k];
            acc[m] += a.x*w0 + a.y*w1 + a.z*w2 + a.w*w3;
        }
    }
    float b1 = bs1[t];
#pragma unroll
    for (int m = 0; m < 16; m++) Hs[m][t] = sspf(acc[m] + b1);
    __syncthreads();

#pragma unroll
    for (int m = 0; m < 16; m++) acc[m] = 0.0f;
    for (int k = 0; k < HH; k += 4){
        float w0 = Ws2[(k+0)*HH+t], w1 = Ws2[(k+1)*HH+t];
        float w2 = Ws2[(k+2)*HH+t], w3 = Ws2[(k+3)*HH+t];
#pragma unroll
        for (int m = 0; m < 16; m++){
            float4 a = *(const float4*)&Hs[m][k];
            acc[m] += a.x*w0 + a.y*w1 + a.z*w2 + a.w*w3;
        }
    }
    float b2 = bs2[t];
#pragma unroll
    for (int m = 0; m < 16; m++){
        int idx = (row0+m)*HH + t;
        float v = g_state[idx] + acc[m] + b2;
        g_state[idx] = v;
        out[idx] = v;
    }
}

// ---------------------------------------------------------------------------
extern "C" void kernel_launch(void* const* d_in, const int* in_sizes, int n_in,
                              void* d_out, int out_size)
{
    const int*   nodes      = (const int*)  d_in[0];
    const int*   atom_edges = (const int*)  d_in[1];
    const float* feats      = (const float*)d_in[2];
    const int*   num_nodes  = (const int*)  d_in[3];
    // d_in[4] = num_atom_edges (all == EP, unused)
    const float* emb = (const float*)d_in[5];
    const float* Wn1 = (const float*)d_in[6];
    const float* bn1 = (const float*)d_in[7];
    const float* Wn2 = (const float*)d_in[8];
    const float* bn2 = (const float*)d_in[9];
    const float* We1 = (const float*)d_in[10];
    const float* be1 = (const float*)d_in[11];
    const float* We2 = (const float*)d_in[12];
    const float* be2 = (const float*)d_in[13];
    const float* Ws1 = (const float*)d_in[14];
    const float* bs1 = (const float*)d_in[15];
    const float* Ws2 = (const float*)d_in[16];
    const float* bs2 = (const float*)d_in[17];
    float* out = (float*)d_out;

    cudaFuncSetAttribute(k_edge, cudaFuncAttributeMaxDynamicSharedMemorySize,
                         SMEM_WORDS*sizeof(unsigned));

    k_init<<<(NT*HH + 255)/256, 256>>>(nodes, emb, num_nodes);
    for (int l = 0; l < NL; l++){
        k_zero<<<(NT*HH + 255)/256, 256>>>();
        k_pre<<<NT/16, 256>>>(Wn1 + l*2*HH*HH);
        k_edge<<<GRID_EDGE, 256, SMEM_WORDS*sizeof(unsigned)>>>(atom_edges, feats,
            bn1 + l*HH, Wn2 + l*HH*HH, bn2 + l*HH,
            We1 + l*ES*HH, be1 + l*HH, We2 + l*HH*HH, be2 + l*HH);
        k_upd<<<NT/16, 128>>>(Ws1 + l*HH*HH, bs1 + l*HH,
                              Ws2 + l*HH*HH, bs2 + l*HH,
                              out + (size_t)l*NT*HH);
    }
}

// round 7
// speedup vs baseline: 3.8823x; 1.2426x over previous
#include <cuda_runtime.h>
#include <math.h>

#define BB 8
#define NP 2048
#define EP 32768
#define NT (BB*NP)      // 16384 total nodes
#define ET (BB*EP)      // 262144 total edges
#define HH 128
#define NL 3
#define ES 50

// ---- edge-kernel tiling ----
#define MT 32                   // edges per tile
#define NTILES (ET/MT)          // 8192
#define GRID_EDGE 296           // 2 blocks/SM

// smem layout in 32-bit WORDS (each word = bf16x2).
// strides ≡ 4 (mod 32) -> each 8-row ldmatrix phase hits 8 distinct 4-word
// bank groups (conflict-free); all row bases multiples of 4 words (16B).
#define A1S 68
#define A2S 68
#define W1S 36
#define W2S 68
#define OFF_A1 0
#define OFF_A2 (OFF_A1 + MT*A1S)        // 2176
#define OFF_W1 (OFF_A2 + MT*A2S)        // 4352
#define OFF_W2 (OFF_W1 + HH*W1S)        // 8960
#define OFF_W3 (OFF_W2 + HH*W2S)        // 17664
#define SMEM_WORDS (OFF_W3 + HH*W2S)    // 26368 words = 105472 B

// ---- scratch (no allocations allowed; __device__ globals) ----
__device__ float g_state[NT*HH];
__device__ float g_S[NT*HH];
__device__ float g_R[NT*HH];
__device__ float g_msum[NT*HH];
__device__ int   g_off[BB];

__device__ __forceinline__ float sspf(float x){
    return fmaxf(x, 0.0f) + __logf(1.0f + __expf(-fabsf(x))) - 0.69314718055994530942f;
}
__device__ __forceinline__ unsigned bf2(float lo, float hi){
    unsigned r; asm("cvt.rn.bf16x2.f32 %0, %1, %2;" : "=r"(r) : "f"(hi), "f"(lo)); return r;
}
__device__ __forceinline__ void mma16(float* d, unsigned a0, unsigned a1, unsigned a2,
                                      unsigned a3, unsigned b0, unsigned b1){
    asm volatile("mma.sync.aligned.m16n8k16.row.col.f32.bf16.bf16.f32 "
        "{%0,%1,%2,%3},{%4,%5,%6,%7},{%8,%9},{%0,%1,%2,%3};"
        : "+f"(d[0]),"+f"(d[1]),"+f"(d[2]),"+f"(d[3])
        : "r"(a0),"r"(a1),"r"(a2),"r"(a3),"r"(b0),"r"(b1));
}
__device__ __forceinline__ void ldsm4(unsigned addr, unsigned& d0, unsigned& d1,
                                      unsigned& d2, unsigned& d3){
    asm volatile("ldmatrix.sync.aligned.m8n8.x4.shared.b16 {%0,%1,%2,%3}, [%4];"
        : "=r"(d0),"=r"(d1),"=r"(d2),"=r"(d3) : "r"(addr));
}
__device__ __forceinline__ float gsf(float d, int j){
    if (j >= ES) return 0.0f;
    float dd = d - 0.1f*(float)j;
    return __expf(-dd*dd*50.0f);
}

// ---------------------------------------------------------------------------
__global__ void k_init(const int* __restrict__ nodes, const float* __restrict__ emb,
                       const int* __restrict__ num_nodes){
    int i = blockIdx.x*blockDim.x + threadIdx.x;
    if (i == 0){
        int acc = 0;
        for (int b = 0; b < BB; b++){ g_off[b] = acc; acc += num_nodes[b]; }
    }
    if (i < NT*HH){
        int node = i >> 7, c = i & 127;
        g_state[i] = emb[nodes[node]*HH + c];
    }
}

// ---------------------------------------------------------------------------
// node pre-GEMM (+ fused msum zeroing): S = state @ Wn1[:128], R = state @ Wn1[128:]
// ---------------------------------------------------------------------------
__global__ void k_pre(const float* __restrict__ Wn1){
    __shared__ __align__(16) float As[16][HH];
    int t = threadIdx.x;
    int row0 = blockIdx.x*16;
    // fused k_zero: this block's 16-row slice of g_msum
    for (int i = t; i < 16*HH; i += 256)
        g_msum[row0*HH + i] = 0.0f;
    for (int i = t; i < 16*HH; i += 256)
        As[i>>7][i&127] = g_state[(row0 + (i>>7))*HH + (i&127)];
    __syncthreads();

    int half = t >> 7;
    int col  = t & 127;
    const float* W = Wn1 + half*HH*HH + col;
    float acc[16];
#pragma unroll
    for (int m = 0; m < 16; m++) acc[m] = 0.0f;
    for (int k = 0; k < HH; k += 4){
        float w0 = W[(k+0)*HH], w1 = W[(k+1)*HH], w2 = W[(k+2)*HH], w3 = W[(k+3)*HH];
#pragma unroll
        for (int m = 0; m < 16; m++){
            float4 a = *(const float4*)&As[m][k];
            acc[m] += a.x*w0 + a.y*w1 + a.z*w2 + a.w*w3;
        }
    }
    float* dst = half ? g_R : g_S;
#pragma unroll
    for (int m = 0; m < 16; m++) dst[(row0+m)*HH + col] = acc[m];
}

// ---------------------------------------------------------------------------
// persistent bf16 tensor-core edge kernel; ldmatrix fragment loads.
// 8 warps: mt = w&1 (rows mt*16..+15), nq = w>>1 (cols nq*32..+31)
// ---------------------------------------------------------------------------
__global__ void __launch_bounds__(256, 2) k_edge(
    const int* __restrict__ atom_edges, const float* __restrict__ feats,
    const float* __restrict__ bn1, const float* __restrict__ Wn2, const float* __restrict__ bn2,
    const float* __restrict__ We1, const float* __restrict__ be1,
    const float* __restrict__ We2, const float* __restrict__ be2)
{
    extern __shared__ unsigned smw[];
    int t = threadIdx.x, lane = t & 31, w = t >> 5;
    int g = lane >> 2, tid = lane & 3;

    // ---- stage weights transposed as bf16x2 words: Wt[n][kw] ----
    for (int i = t; i < HH*32; i += 256){          // We1: K=50 padded to 64
        int n = i & 127, kw = i >> 7, k = 2*kw;
        float lo = (k   < ES) ? We1[(k  )*HH + n] : 0.0f;
        float hi = (k+1 < ES) ? We1[(k+1)*HH + n] : 0.0f;
        smw[OFF_W1 + n*W1S + kw] = bf2(lo, hi);
    }
    for (int i = t; i < HH*64; i += 256){
        int n = i & 127, kw = i >> 7, k = 2*kw;
        smw[OFF_W2 + n*W2S + kw] = bf2(Wn2[k*HH + n], Wn2[(k+1)*HH + n]);
        smw[OFF_W3 + n*W2S + kw] = bf2(We2[k*HH + n], We2[(k+1)*HH + n]);
    }

    // ---- per-thread coords ----
    int mt = w & 1, nq = w >> 1;
    int r0 = mt*16 + g, r1 = r0 + 8;
    int fc = (t & 63)*2;       // fill column pair
    int fr = t >> 6;           // fill row base (0..3)
    float bn1a = bn1[fc], bn1b = bn1[fc+1];

    // hoisted epilogue biases (constant per layer)
    float bn2h[4][2], be2h[4][2];
#pragma unroll
    for (int ntl = 0; ntl < 4; ntl++){
        int c0 = nq*32 + ntl*8 + 2*tid;
        bn2h[ntl][0] = bn2[c0]; bn2h[ntl][1] = bn2[c0+1];
        be2h[ntl][0] = be2[c0]; be2h[ntl][1] = be2[c0+1];
    }

    // ---- ldmatrix per-lane addresses (bytes) ----
    unsigned sb = (unsigned)__cvta_generic_to_shared(smw);
    // A frags: matrices (rows lo, kw), (rows hi, kw), (rows lo, kw+4), (rows hi, kw+4)
    int rowA = mt*16 + (lane & 7) + ((lane >> 3) & 1)*8;
    int kSel = (lane >> 4)*4;
    unsigned aA1 = sb + (unsigned)(OFF_A1 + rowA*A1S + kSel)*4u;
    unsigned aA2 = sb + (unsigned)(OFF_A2 + rowA*A2S + kSel)*4u;
    // B frags: matrices = 4 consecutive 4-word chunks of row (nbase + lane&7)
    int rowBn = nq*32 + (lane & 7);
    int bSel  = (lane >> 3)*4;
    unsigned aW1 = sb + (unsigned)(OFF_W1 + rowBn*W1S + bSel)*4u;
    unsigned aW2 = sb + (unsigned)(OFF_W2 + rowBn*W2S + bSel)*4u;
    unsigned aW3 = sb + (unsigned)(OFF_W3 + rowBn*W2S + bSel)*4u;
    const unsigned W1STEP = 8u*W1S*4u;   // ntl stride
    const unsigned W2STEP = 8u*W2S*4u;

    for (int tile = blockIdx.x; tile < NTILES; tile += gridDim.x){
        __syncthreads();
        int e0t = tile*MT;
        int off = g_off[tile >> 10];

        // ---- issue gather loads for A1 (latency hidden under GEMM1) ----
        float2 sv[8], rv[8];
#pragma unroll
        for (int j = 0; j < 8; j++){
            int e  = e0t + fr + 4*j;
            int sn = atom_edges[2*e]   + off;
            int rc = atom_edges[2*e+1] + off;
            sv[j] = *(const float2*)&g_S[sn*HH + fc];
            rv[j] = *(const float2*)&g_R[rc*HH + fc];
        }

        // ---- GEMM1: es (regs) @ We1^T -> A2 ----
        float dr0f = feats[e0t + r0], dr1f = feats[e0t + r1];
        float d1[4][4];
#pragma unroll
        for (int i = 0; i < 4; i++)
#pragma unroll
            for (int j = 0; j < 4; j++) d1[i][j] = 0.0f;
#pragma unroll
        for (int kt2 = 0; kt2 < 2; kt2++){
            int k0 = kt2*32;
            unsigned a0 = bf2(gsf(dr0f, k0+2*tid   ), gsf(dr0f, k0+2*tid+1 ));
            unsigned a1 = bf2(gsf(dr1f, k0+2*tid   ), gsf(dr1f, k0+2*tid+1 ));
            unsigned a2 = bf2(gsf(dr0f, k0+2*tid+8 ), gsf(dr0f, k0+2*tid+9 ));
            unsigned a3 = bf2(gsf(dr1f, k0+2*tid+8 ), gsf(dr1f, k0+2*tid+9 ));
            unsigned a4 = bf2(gsf(dr0f, k0+2*tid+16), gsf(dr0f, k0+2*tid+17));
            unsigned a5 = bf2(gsf(dr1f, k0+2*tid+16), gsf(dr1f, k0+2*tid+17));
            unsigned a6 = bf2(gsf(dr0f, k0+2*tid+24), gsf(dr0f, k0+2*tid+25));
            unsigned a7 = bf2(gsf(dr1f, k0+2*tid+24), gsf(dr1f, k0+2*tid+25));
#pragma unroll
            for (int ntl = 0; ntl < 4; ntl++){
                unsigned b0,b1,b2,b3;
                ldsm4(aW1 + ntl*W1STEP + kt2*64u, b0,b1,b2,b3);
                mma16(d1[ntl], a0,a1,a2,a3, b0,b1);
                mma16(d1[ntl], a4,a5,a6,a7, b2,b3);
            }
        }
        // write A2 = bf16(ssp(d1 + be1))
#pragma unroll
        for (int ntl = 0; ntl < 4; ntl++){
            int c0 = nq*32 + ntl*8 + 2*tid;
            float e1 = be1[c0], e2 = be1[c0+1];
            int cw = c0 >> 1;
            smw[OFF_A2 + r0*A2S + cw] = bf2(sspf(d1[ntl][0]+e1), sspf(d1[ntl][1]+e2));
            smw[OFF_A2 + r1*A2S + cw] = bf2(sspf(d1[ntl][2]+e1), sspf(d1[ntl][3]+e2));
        }
        // write A1 = bf16(ssp(S+R+bn1))
#pragma unroll
        for (int j = 0; j < 8; j++){
            int m = fr + 4*j;
            smw[OFF_A1 + m*A1S + (t & 63)] =
                bf2(sspf(sv[j].x + rv[j].x + bn1a), sspf(sv[j].y + rv[j].y + bn1b));
        }
        __syncthreads();

        // ---- GEMM2: mn = A1 @ Wn2^T ; GEMM3: gt = A2 @ We2^T ----
        float dm[4][4], dg[4][4];
#pragma unroll
        for (int i = 0; i < 4; i++)
#pragma unroll
            for (int j = 0; j < 4; j++){ dm[i][j] = 0.0f; dg[i][j] = 0.0f; }

#pragma unroll
        for (int kt2 = 0; kt2 < 4; kt2++){
            unsigned a0,a1,a2,a3, a4,a5,a6,a7;
            ldsm4(aA1 + kt2*64u,       a0,a1,a2,a3);   // frags for kt = 2*kt2
            ldsm4(aA1 + kt2*64u + 32u, a4,a5,a6,a7);   // frags for kt+1
#pragma unroll
            for (int ntl = 0; ntl < 4; ntl++){
                unsigned b0,b1,b2,b3;
                ldsm4(aW2 + ntl*W2STEP + kt2*64u, b0,b1,b2,b3);
                mma16(dm[ntl], a0,a1,a2,a3, b0,b1);
                mma16(dm[ntl], a4,a5,a6,a7, b2,b3);
            }
        }
#pragma unroll
        for (int kt2 = 0; kt2 < 4; kt2++){
            unsigned a0,a1,a2,a3, a4,a5,a6,a7;
            ldsm4(aA2 + kt2*64u,       a0,a1,a2,a3);
            ldsm4(aA2 + kt2*64u + 32u, a4,a5,a6,a7);
#pragma unroll
            for (int ntl = 0; ntl < 4; ntl++){
                unsigned b0,b1,b2,b3;
                ldsm4(aW3 + ntl*W2STEP + kt2*64u, b0,b1,b2,b3);
                mma16(dg[ntl], a0,a1,a2,a3, b0,b1);
                mma16(dg[ntl], a4,a5,a6,a7, b2,b3);
            }
        }

        // ---- combine + scatter ----
        float cut0 = 1.0f/(1.0f + __expf(5.0f*(dr0f - 3.5f)));
        float cut1 = 1.0f/(1.0f + __expf(5.0f*(dr1f - 3.5f)));
        int rcv0 = atom_edges[2*(e0t + r0) + 1] + off;
        int rcv1 = atom_edges[2*(e0t + r1) + 1] + off;
#pragma unroll
        for (int ntl = 0; ntl < 4; ntl++){
            int c0 = nq*32 + ntl*8 + 2*tid;
            float n0 = bn2h[ntl][0], n1 = bn2h[ntl][1];
            float q0 = be2h[ntl][0], q1 = be2h[ntl][1];
            atomicAdd(&g_msum[rcv0*HH + c0  ], (dm[ntl][0]+n0) * ((dg[ntl][0]+q0)*cut0));
            atomicAdd(&g_msum[rcv0*HH + c0+1], (dm[ntl][1]+n1) * ((dg[ntl][1]+q1)*cut0));
            atomicAdd(&g_msum[rcv1*HH + c0  ], (dm[ntl][2]+n0) * ((dg[ntl][2]+q0)*cut1));
            atomicAdd(&g_msum[rcv1*HH + c0+1], (dm[ntl][3]+n1) * ((dg[ntl][3]+q1)*cut1));
        }
    }
}

// ---------------------------------------------------------------------------
// node update: state += ssp(msum @ Ws1 + bs1) @ Ws2 + bs2 ; write out slab
// ---------------------------------------------------------------------------
__global__ void k_upd(const float* __restrict__ Ws1, const float* __restrict__ bs1,
                      const float* __restrict__ Ws2, const float* __restrict__ bs2,
                      float* __restrict__ out)
{
    __shared__ __align__(16) float As[16][HH];
    __shared__ __align__(16) float Hs[16][HH];
    int t = threadIdx.x;
    int row0 = blockIdx.x*16;
    for (int i = t; i < 16*HH; i += 128)
        As[i>>7][i&127] = g_msum[(row0 + (i>>7))*HH + (i&127)];
    __syncthreads();

    float acc[16];
#pragma unroll
    for (int m = 0; m < 16; m++) acc[m] = 0.0f;
    for (int k = 0; k < HH; k += 4){
        float w0 = Ws1[(k+0)*HH+t], w1 = Ws1[(k+1)*HH+t];
        float w2 = Ws1[(k+2)*HH+t], w3 = Ws1[(k+3)*HH+t];
#pragma unroll
        for (int m = 0; m < 16; m++){
            float4 a = *(const float4*)&As[m][k];
            acc[m] += a.x*w0 + a.y*w1 + a.z*w2 + a.w*w3;
        }
    }
    float b1 = bs1[t];
#pragma unroll
    for (int m = 0; m < 16; m++) Hs[m][t] = sspf(acc[m] + b1);
    __syncthreads();

#pragma unroll
    for (int m = 0; m < 16; m++) acc[m] = 0.0f;
    for (int k = 0; k < HH; k += 4){
        float w0 = Ws2[(k+0)*HH+t], w1 = Ws2[(k+1)*HH+t];
        float w2 = Ws2[(k+2)*HH+t], w3 = Ws2[(k+3)*HH+t];
#pragma unroll
        for (int m = 0; m < 16; m++){
            float4 a = *(const float4*)&Hs[m][k];
            acc[m] += a.x*w0 + a.y*w1 + a.z*w2 + a.w*w3;
        }
    }
    float b2 = bs2[t];
#pragma unroll
    for (int m = 0; m < 16; m++){
        int idx = (row0+m)*HH + t;
        float v = g_state[idx] + acc[m] + b2;
        g_state[idx] = v;
        out[idx] = v;
    }
}

// ---------------------------------------------------------------------------
extern "C" void kernel_launch(void* const* d_in, const int* in_sizes, int n_in,
                              void* d_out, int out_size)
{
    const int*   nodes      = (const int*)  d_in[0];
    const int*   atom_edges = (const int*)  d_in[1];
    const float* feats      = (const float*)d_in[2];
    const int*   num_nodes  = (const int*)  d_in[3];
    // d_in[4] = num_atom_edges (all == EP, unused)
    const float* emb = (const float*)d_in[5];
    const float* Wn1 = (const float*)d_in[6];
    const float* bn1 = (const float*)d_in[7];
    const float* Wn2 = (const float*)d_in[8];
    const float* bn2 = (const float*)d_in[9];
    const float* We1 = (const float*)d_in[10];
    const float* be1 = (const float*)d_in[11];
    const float* We2 = (const float*)d_in[12];
    const float* be2 = (const float*)d_in[13];
    const float* Ws1 = (const float*)d_in[14];
    const float* bs1 = (const float*)d_in[15];
    const float* Ws2 = (const float*)d_in[16];
    const float* bs2 = (const float*)d_in[17];
    float* out = (float*)d_out;

    cudaFuncSetAttribute(k_edge, cudaFuncAttributeMaxDynamicSharedMemorySize,
                         SMEM_WORDS*sizeof(unsigned));

    k_init<<<(NT*HH + 255)/256, 256>>>(nodes, emb, num_nodes);
    for (int l = 0; l < NL; l++){
        k_pre<<<NT/16, 256>>>(Wn1 + l*2*HH*HH);
        k_edge<<<GRID_EDGE, 256, SMEM_WORDS*sizeof(unsigned)>>>(atom_edges, feats,
            bn1 + l*HH, Wn2 + l*HH*HH, bn2 + l*HH,
            We1 + l*ES*HH, be1 + l*HH, We2 + l*HH*HH, be2 + l*HH);
        k_upd<<<NT/16, 128>>>(Ws1 + l*HH*HH, bs1 + l*HH,
                              Ws2 + l*HH*HH, bs2 + l*HH,
                              out + (size_t)l*NT*HH);
    }
}

// round 8
// speedup vs baseline: 5.2821x; 1.3605x over previous
#include <cuda_runtime.h>
#include <math.h>

#define BB 8
#define NP 2048
#define EP 32768
#define NT (BB*NP)      // 16384 total nodes
#define ET (BB*EP)      // 262144 total edges
#define HH 128
#define NL 3
#define ES 50

// ---- edge-kernel tiling ----
#define MT 32
#define NTILES (ET/MT)          // 8192
#define GRID_EDGE 296           // 2 blocks/SM

// edge-kernel smem (words of bf16x2); strides ≡ 4 (mod 32) -> conflict-free ldmatrix
#define A1S 68
#define A2S 68
#define W1S 36
#define W2S 68
#define OFF_A1 0
#define OFF_A2 (OFF_A1 + MT*A1S)
#define OFF_W1 (OFF_A2 + MT*A2S)
#define OFF_W2 (OFF_W1 + HH*W1S)
#define OFF_W3 (OFF_W2 + HH*W2S)
#define SMEM_WORDS (OFF_W3 + HH*W2S)    // 26368 words

// node-kernel smem layouts (stride 68 words everywhere)
#define NS 68
#define OFFP_A 0
#define OFFP_W (OFFP_A + 64*NS)         // 4352
#define SMEM_PRE (OFFP_W + 256*NS)      // 21760 words = 87040 B
#define OFFU_A 0
#define OFFU_H (OFFU_A + 64*NS)         // 4352
#define OFFU_W1 (OFFU_H + 64*NS)        // 8704
#define OFFU_W2 (OFFU_W1 + HH*NS)       // 17408
#define SMEM_UPD (OFFU_W2 + HH*NS)      // 26112 words = 104448 B

// transposed bf16 weight scratch: per layer: pre 16384 w, s1 8192 w, s2 8192 w
#define GWT_PRE(l) ((l)*16384)
#define GWT_S1(l)  (49152 + (l)*8192)
#define GWT_S2(l)  (73728 + (l)*8192)

// ---- scratch (no allocations allowed; __device__ globals) ----
__device__ float g_state[NT*HH];
__device__ float g_S[NT*HH];
__device__ float g_R[NT*HH];
__device__ float g_msum[NT*HH];
__device__ int   g_off[BB];
__device__ __align__(16) unsigned g_wt[98304];

__device__ __forceinline__ float sspf(float x){
    return fmaxf(x, 0.0f) + __logf(1.0f + __expf(-fabsf(x))) - 0.69314718055994530942f;
}
__device__ __forceinline__ unsigned bf2(float lo, float hi){
    unsigned r; asm("cvt.rn.bf16x2.f32 %0, %1, %2;" : "=r"(r) : "f"(hi), "f"(lo)); return r;
}
__device__ __forceinline__ void mma16(float* d, unsigned a0, unsigned a1, unsigned a2,
                                      unsigned a3, unsigned b0, unsigned b1){
    asm volatile("mma.sync.aligned.m16n8k16.row.col.f32.bf16.bf16.f32 "
        "{%0,%1,%2,%3},{%4,%5,%6,%7},{%8,%9},{%0,%1,%2,%3};"
        : "+f"(d[0]),"+f"(d[1]),"+f"(d[2]),"+f"(d[3])
        : "r"(a0),"r"(a1),"r"(a2),"r"(a3),"r"(b0),"r"(b1));
}
__device__ __forceinline__ void ldsm4(unsigned addr, unsigned& d0, unsigned& d1,
                                      unsigned& d2, unsigned& d3){
    asm volatile("ldmatrix.sync.aligned.m8n8.x4.shared.b16 {%0,%1,%2,%3}, [%4];"
        : "=r"(d0),"=r"(d1),"=r"(d2),"=r"(d3) : "r"(addr));
}
__device__ __forceinline__ float gsf(float d, int j){
    if (j >= ES) return 0.0f;
    float dd = d - 0.1f*(float)j;
    return __expf(-dd*dd*50.0f);
}

// ---------------------------------------------------------------------------
__global__ void k_init(const int* __restrict__ nodes, const float* __restrict__ emb,
                       const int* __restrict__ num_nodes){
    int i = blockIdx.x*blockDim.x + threadIdx.x;
    if (i == 0){
        int acc = 0;
        for (int b = 0; b < BB; b++){ g_off[b] = acc; acc += num_nodes[b]; }
    }
    if (i < NT*HH){
        int node = i >> 7, c = i & 127;
        g_state[i] = emb[nodes[node]*HH + c];
    }
}

// ---------------------------------------------------------------------------
// one-shot: transpose+convert node-path weights for ALL layers into g_wt
// ---------------------------------------------------------------------------
__global__ void k_wt(const float* __restrict__ Wn1, const float* __restrict__ Ws1,
                     const float* __restrict__ Ws2){
    int i = blockIdx.x*blockDim.x + threadIdx.x;
    if (i >= 3*32768) return;
    int l = i / 32768, r = i - l*32768;
    if (r < 16384){
        int c = r >> 6, kw = r & 63;
        int half = c >> 7, n = c & 127;
        const float* W = Wn1 + l*2*HH*HH + half*HH*HH;
        g_wt[GWT_PRE(l) + r] = bf2(W[(2*kw)*HH + n], W[(2*kw+1)*HH + n]);
    } else if (r < 24576){
        int q = r - 16384; int n = q >> 6, kw = q & 63;
        const float* W = Ws1 + l*HH*HH;
        g_wt[GWT_S1(l) + q] = bf2(W[(2*kw)*HH + n], W[(2*kw+1)*HH + n]);
    } else {
        int q = r - 24576; int n = q >> 6, kw = q & 63;
        const float* W = Ws2 + l*HH*HH;
        g_wt[GWT_S2(l) + q] = bf2(W[(2*kw)*HH + n], W[(2*kw+1)*HH + n]);
    }
}

// ---------------------------------------------------------------------------
// node pre-GEMM (bf16 mma): [S|R] = state @ Wn1  (M=64/block, N=256, K=128)
// also zeroes this block's g_msum slice (fused k_zero)
// ---------------------------------------------------------------------------
__global__ void __launch_bounds__(256, 2) k_pre(int layer){
    extern __shared__ unsigned smw[];
    int t = threadIdx.x, lane = t & 31, w = t >> 5;
    int g = lane >> 2, tid = lane & 3;
    int row0 = blockIdx.x*64;

    // fused zero of msum slice
    for (int i = t; i < 64*HH/4; i += 256)
        ((float4*)g_msum)[row0*HH/4 + i] = make_float4(0.f,0.f,0.f,0.f);

    // stage A: state rows -> bf16
    for (int i = t; i < 64*64; i += 256){
        int r = i >> 6, kw = i & 63;
        float2 v = *(const float2*)&g_state[(row0 + r)*HH + 2*kw];
        smw[OFFP_A + r*NS + kw] = bf2(v.x, v.y);
    }
    // stage W^T via uint4 (4096 vec4 words)
    {
        const uint4* src = (const uint4*)(g_wt + GWT_PRE(layer));
        for (int i = t; i < 4096; i += 256){
            int n = i >> 4, kq = i & 15;
            *(uint4*)&smw[OFFP_W + n*NS + kq*4] = src[i];
        }
    }
    __syncthreads();

    int wm = w & 1, wn = w >> 1;       // 2 M-groups (32 rows), 4 N-groups (64 cols)
    float d0[8][4], d1[8][4];
#pragma unroll
    for (int n = 0; n < 8; n++)
#pragma unroll
        for (int j = 0; j < 4; j++){ d0[n][j] = 0.f; d1[n][j] = 0.f; }

    unsigned sb = (unsigned)__cvta_generic_to_shared(smw);
    int rowA = wm*32 + (lane & 7) + ((lane >> 3) & 1)*8;
    int kSel = (lane >> 4)*4;
    unsigned aA0 = sb + (unsigned)(OFFP_A + rowA*NS + kSel)*4u;
    unsigned aA1 = aA0 + 16u*NS*4u;
    int rowBn = wn*64 + (lane & 7);
    int bSel  = (lane >> 3)*4;
    unsigned aW = sb + (unsigned)(OFFP_W + rowBn*NS + bSel)*4u;
    const unsigned NSTEP = 8u*NS*4u;

#pragma unroll
    for (int kt2 = 0; kt2 < 4; kt2++){
        unsigned p0,p1,p2,p3, p4,p5,p6,p7;
        unsigned q0,q1,q2,q3, q4,q5,q6,q7;
        ldsm4(aA0 + kt2*64u,       p0,p1,p2,p3);
        ldsm4(aA0 + kt2*64u + 32u, p4,p5,p6,p7);
        ldsm4(aA1 + kt2*64u,       q0,q1,q2,q3);
        ldsm4(aA1 + kt2*64u + 32u, q4,q5,q6,q7);
#pragma unroll
        for (int ntl = 0; ntl < 8; ntl++){
            unsigned b0,b1,b2,b3;
            ldsm4(aW + ntl*NSTEP + kt2*64u, b0,b1,b2,b3);
            mma16(d0[ntl], p0,p1,p2,p3, b0,b1);
            mma16(d0[ntl], p4,p5,p6,p7, b2,b3);
            mma16(d1[ntl], q0,q1,q2,q3, b0,b1);
            mma16(d1[ntl], q4,q5,q6,q7, b2,b3);
        }
    }

    // epilogue: fp32 stores to g_S / g_R
    float* dst = (wn >= 2) ? g_R : g_S;
#pragma unroll
    for (int ntl = 0; ntl < 8; ntl++){
        int c  = wn*64 + ntl*8 + 2*tid;
        int cc = c & 127;
        int r0 = row0 + wm*32 + g, r1 = r0 + 8;
        *(float2*)&dst[r0*HH + cc] = make_float2(d0[ntl][0], d0[ntl][1]);
        *(float2*)&dst[r1*HH + cc] = make_float2(d0[ntl][2], d0[ntl][3]);
        *(float2*)&dst[(r0+16)*HH + cc] = make_float2(d1[ntl][0], d1[ntl][1]);
        *(float2*)&dst[(r1+16)*HH + cc] = make_float2(d1[ntl][2], d1[ntl][3]);
    }
}

// ---------------------------------------------------------------------------
// persistent bf16 tensor-core edge kernel (unchanged from R7)
// ---------------------------------------------------------------------------
__global__ void __launch_bounds__(256, 2) k_edge(
    const int* __restrict__ atom_edges, const float* __restrict__ feats,
    const float* __restrict__ bn1, const float* __restrict__ Wn2, const float* __restrict__ bn2,
    const float* __restrict__ We1, const float* __restrict__ be1,
    const float* __restrict__ We2, const float* __restrict__ be2)
{
    extern __shared__ unsigned smw[];
    int t = threadIdx.x, lane = t & 31, w = t >> 5;
    int g = lane >> 2, tid = lane & 3;

    for (int i = t; i < HH*32; i += 256){
        int n = i & 127, kw = i >> 7, k = 2*kw;
        float lo = (k   < ES) ? We1[(k  )*HH + n] : 0.0f;
        float hi = (k+1 < ES) ? We1[(k+1)*HH + n] : 0.0f;
        smw[OFF_W1 + n*W1S + kw] = bf2(lo, hi);
    }
    for (int i = t; i < HH*64; i += 256){
        int n = i & 127, kw = i >> 7, k = 2*kw;
        smw[OFF_W2 + n*W2S + kw] = bf2(Wn2[k*HH + n], Wn2[(k+1)*HH + n]);
        smw[OFF_W3 + n*W2S + kw] = bf2(We2[k*HH + n], We2[(k+1)*HH + n]);
    }

    int mt = w & 1, nq = w >> 1;
    int r0 = mt*16 + g, r1 = r0 + 8;
    int fc = (t & 63)*2;
    int fr = t >> 6;
    float bn1a = bn1[fc], bn1b = bn1[fc+1];

    float bn2h[4][2], be2h[4][2];
#pragma unroll
    for (int ntl = 0; ntl < 4; ntl++){
        int c0 = nq*32 + ntl*8 + 2*tid;
        bn2h[ntl][0] = bn2[c0]; bn2h[ntl][1] = bn2[c0+1];
        be2h[ntl][0] = be2[c0]; be2h[ntl][1] = be2[c0+1];
    }

    unsigned sb = (unsigned)__cvta_generic_to_shared(smw);
    int rowA = mt*16 + (lane & 7) + ((lane >> 3) & 1)*8;
    int kSel = (lane >> 4)*4;
    unsigned aA1 = sb + (unsigned)(OFF_A1 + rowA*A1S + kSel)*4u;
    unsigned aA2 = sb + (unsigned)(OFF_A2 + rowA*A2S + kSel)*4u;
    int rowBn = nq*32 + (lane & 7);
    int bSel  = (lane >> 3)*4;
    unsigned aW1 = sb + (unsigned)(OFF_W1 + rowBn*W1S + bSel)*4u;
    unsigned aW2 = sb + (unsigned)(OFF_W2 + rowBn*W2S + bSel)*4u;
    unsigned aW3 = sb + (unsigned)(OFF_W3 + rowBn*W2S + bSel)*4u;
    const unsigned W1STEP = 8u*W1S*4u;
    const unsigned W2STEP = 8u*W2S*4u;

    for (int tile = blockIdx.x; tile < NTILES; tile += gridDim.x){
        __syncthreads();
        int e0t = tile*MT;
        int off = g_off[tile >> 10];

        float2 sv[8], rv[8];
#pragma unroll
        for (int j = 0; j < 8; j++){
            int e  = e0t + fr + 4*j;
            int sn = atom_edges[2*e]   + off;
            int rc = atom_edges[2*e+1] + off;
            sv[j] = *(const float2*)&g_S[sn*HH + fc];
            rv[j] = *(const float2*)&g_R[rc*HH + fc];
        }

        float dr0f = feats[e0t + r0], dr1f = feats[e0t + r1];
        float d1[4][4];
#pragma unroll
        for (int i = 0; i < 4; i++)
#pragma unroll
            for (int j = 0; j < 4; j++) d1[i][j] = 0.0f;
#pragma unroll
        for (int kt2 = 0; kt2 < 2; kt2++){
            int k0 = kt2*32;
            unsigned a0 = bf2(gsf(dr0f, k0+2*tid   ), gsf(dr0f, k0+2*tid+1 ));
            unsigned a1 = bf2(gsf(dr1f, k0+2*tid   ), gsf(dr1f, k0+2*tid+1 ));
            unsigned a2 = bf2(gsf(dr0f, k0+2*tid+8 ), gsf(dr0f, k0+2*tid+9 ));
            unsigned a3 = bf2(gsf(dr1f, k0+2*tid+8 ), gsf(dr1f, k0+2*tid+9 ));
            unsigned a4 = bf2(gsf(dr0f, k0+2*tid+16), gsf(dr0f, k0+2*tid+17));
            unsigned a5 = bf2(gsf(dr1f, k0+2*tid+16), gsf(dr1f, k0+2*tid+17));
            unsigned a6 = bf2(gsf(dr0f, k0+2*tid+24), gsf(dr0f, k0+2*tid+25));
            unsigned a7 = bf2(gsf(dr1f, k0+2*tid+24), gsf(dr1f, k0+2*tid+25));
#pragma unroll
            for (int ntl = 0; ntl < 4; ntl++){
                unsigned b0,b1,b2,b3;
                ldsm4(aW1 + ntl*W1STEP + kt2*64u, b0,b1,b2,b3);
                mma16(d1[ntl], a0,a1,a2,a3, b0,b1);
                mma16(d1[ntl], a4,a5,a6,a7, b2,b3);
            }
        }
#pragma unroll
        for (int ntl = 0; ntl < 4; ntl++){
            int c0 = nq*32 + ntl*8 + 2*tid;
            float e1 = be1[c0], e2 = be1[c0+1];
            int cw = c0 >> 1;
            smw[OFF_A2 + r0*A2S + cw] = bf2(sspf(d1[ntl][0]+e1), sspf(d1[ntl][1]+e2));
            smw[OFF_A2 + r1*A2S + cw] = bf2(sspf(d1[ntl][2]+e1), sspf(d1[ntl][3]+e2));
        }
#pragma unroll
        for (int j = 0; j < 8; j++){
            int m = fr + 4*j;
            smw[OFF_A1 + m*A1S + (t & 63)] =
                bf2(sspf(sv[j].x + rv[j].x + bn1a), sspf(sv[j].y + rv[j].y + bn1b));
        }
        __syncthreads();

        float dm[4][4], dg[4][4];
#pragma unroll
        for (int i = 0; i < 4; i++)
#pragma unroll
            for (int j = 0; j < 4; j++){ dm[i][j] = 0.0f; dg[i][j] = 0.0f; }

#pragma unroll
        for (int kt2 = 0; kt2 < 4; kt2++){
            unsigned a0,a1,a2,a3, a4,a5,a6,a7;
            ldsm4(aA1 + kt2*64u,       a0,a1,a2,a3);
            ldsm4(aA1 + kt2*64u + 32u, a4,a5,a6,a7);
#pragma unroll
            for (int ntl = 0; ntl < 4; ntl++){
                unsigned b0,b1,b2,b3;
                ldsm4(aW2 + ntl*W2STEP + kt2*64u, b0,b1,b2,b3);
                mma16(dm[ntl], a0,a1,a2,a3, b0,b1);
                mma16(dm[ntl], a4,a5,a6,a7, b2,b3);
            }
        }
#pragma unroll
        for (int kt2 = 0; kt2 < 4; kt2++){
            unsigned a0,a1,a2,a3, a4,a5,a6,a7;
            ldsm4(aA2 + kt2*64u,       a0,a1,a2,a3);
            ldsm4(aA2 + kt2*64u + 32u, a4,a5,a6,a7);
#pragma unroll
            for (int ntl = 0; ntl < 4; ntl++){
                unsigned b0,b1,b2,b3;
                ldsm4(aW3 + ntl*W2STEP + kt2*64u, b0,b1,b2,b3);
                mma16(dg[ntl], a0,a1,a2,a3, b0,b1);
                mma16(dg[ntl], a4,a5,a6,a7, b2,b3);
            }
        }

        float cut0 = 1.0f/(1.0f + __expf(5.0f*(dr0f - 3.5f)));
        float cut1 = 1.0f/(1.0f + __expf(5.0f*(dr1f - 3.5f)));
        int rcv0 = atom_edges[2*(e0t + r0) + 1] + off;
        int rcv1 = atom_edges[2*(e0t + r1) + 1] + off;
#pragma unroll
        for (int ntl = 0; ntl < 4; ntl++){
            int c0 = nq*32 + ntl*8 + 2*tid;
            float n0 = bn2h[ntl][0], n1 = bn2h[ntl][1];
            float q0 = be2h[ntl][0], q1 = be2h[ntl][1];
            atomicAdd(&g_msum[rcv0*HH + c0  ], (dm[ntl][0]+n0) * ((dg[ntl][0]+q0)*cut0));
            atomicAdd(&g_msum[rcv0*HH + c0+1], (dm[ntl][1]+n1) * ((dg[ntl][1]+q1)*cut0));
            atomicAdd(&g_msum[rcv1*HH + c0  ], (dm[ntl][2]+n0) * ((dg[ntl][2]+q0)*cut1));
            atomicAdd(&g_msum[rcv1*HH + c0+1], (dm[ntl][3]+n1) * ((dg[ntl][3]+q1)*cut1));
        }
    }
}

// ---------------------------------------------------------------------------
// node update (bf16 mma): state += ssp(msum @ Ws1 + bs1) @ Ws2 + bs2
// M=64/block, N=128, K=128, two chained GEMMs
// ---------------------------------------------------------------------------
__global__ void __launch_bounds__(256, 2) k_upd(int layer,
                      const float* __restrict__ bs1, const float* __restrict__ bs2,
                      float* __restrict__ out)
{
    extern __shared__ unsigned smw[];
    int t = threadIdx.x, lane = t & 31, w = t >> 5;
    int g = lane >> 2, tid = lane & 3;
    int row0 = blockIdx.x*64;

    // stage A (msum -> bf16)
    for (int i = t; i < 64*64; i += 256){
        int r = i >> 6, kw = i & 63;
        float2 v = *(const float2*)&g_msum[(row0 + r)*HH + 2*kw];
        smw[OFFU_A + r*NS + kw] = bf2(v.x, v.y);
    }
    // stage Ws1^T, Ws2^T via uint4
    {
        const uint4* s1 = (const uint4*)(g_wt + GWT_S1(layer));
        const uint4* s2 = (const uint4*)(g_wt + GWT_S2(layer));
        for (int i = t; i < 2048; i += 256){
            int n = i >> 4, kq = i & 15;
            *(uint4*)&smw[OFFU_W1 + n*NS + kq*4] = s1[i];
            *(uint4*)&smw[OFFU_W2 + n*NS + kq*4] = s2[i];
        }
    }
    __syncthreads();

    int wm = w & 3, wn = w >> 2;       // 4 M-groups (16 rows), 2 N-groups (64 cols)
    unsigned sb = (unsigned)__cvta_generic_to_shared(smw);
    int rowA = wm*16 + (lane & 7) + ((lane >> 3) & 1)*8;
    int kSel = (lane >> 4)*4;
    unsigned aA  = sb + (unsigned)(OFFU_A + rowA*NS + kSel)*4u;
    unsigned aH  = sb + (unsigned)(OFFU_H + rowA*NS + kSel)*4u;
    int rowBn = wn*64 + (lane & 7);
    int bSel  = (lane >> 3)*4;
    unsigned aW1 = sb + (unsigned)(OFFU_W1 + rowBn*NS + bSel)*4u;
    unsigned aW2 = sb + (unsigned)(OFFU_W2 + rowBn*NS + bSel)*4u;
    const unsigned NSTEP = 8u*NS*4u;

    // GEMM1: msum @ Ws1^T
    float d[8][4];
#pragma unroll
    for (int n = 0; n < 8; n++)
#pragma unroll
        for (int j = 0; j < 4; j++) d[n][j] = 0.f;
#pragma unroll
    for (int kt2 = 0; kt2 < 4; kt2++){
        unsigned a0,a1,a2,a3, a4,a5,a6,a7;
        ldsm4(aA + kt2*64u,       a0,a1,a2,a3);
        ldsm4(aA + kt2*64u + 32u, a4,a5,a6,a7);
#pragma unroll
        for (int ntl = 0; ntl < 8; ntl++){
            unsigned b0,b1,b2,b3;
            ldsm4(aW1 + ntl*NSTEP + kt2*64u, b0,b1,b2,b3);
            mma16(d[ntl], a0,a1,a2,a3, b0,b1);
            mma16(d[ntl], a4,a5,a6,a7, b2,b3);
        }
    }
    // H = bf16(ssp(d + bs1))
    {
        int r0 = wm*16 + g, r1 = r0 + 8;
#pragma unroll
        for (int ntl = 0; ntl < 8; ntl++){
            int c0 = wn*64 + ntl*8 + 2*tid;
            float b1a = bs1[c0], b1b = bs1[c0+1];
            int cw = c0 >> 1;
            smw[OFFU_H + r0*NS + cw] = bf2(sspf(d[ntl][0]+b1a), sspf(d[ntl][1]+b1b));
            smw[OFFU_H + r1*NS + cw] = bf2(sspf(d[ntl][2]+b1a), sspf(d[ntl][3]+b1b));
        }
    }
    __syncthreads();

    // GEMM2: H @ Ws2^T
    float e2[8][4];
#pragma unroll
    for (int n = 0; n < 8; n++)
#pragma unroll
        for (int j = 0; j < 4; j++) e2[n][j] = 0.f;
#pragma unroll
    for (int kt2 = 0; kt2 < 4; kt2++){
        unsigned a0,a1,a2,a3, a4,a5,a6,a7;
        ldsm4(aH + kt2*64u,       a0,a1,a2,a3);
        ldsm4(aH + kt2*64u + 32u, a4,a5,a6,a7);
#pragma unroll
        for (int ntl = 0; ntl < 8; ntl++){
            unsigned b0,b1,b2,b3;
            ldsm4(aW2 + ntl*NSTEP + kt2*64u, b0,b1,b2,b3);
            mma16(e2[ntl], a0,a1,a2,a3, b0,b1);
            mma16(e2[ntl], a4,a5,a6,a7, b2,b3);
        }
    }

    // epilogue: state += e2 + bs2; write out
    {
        int r0 = row0 + wm*16 + g, r1 = r0 + 8;
#pragma unroll
        for (int ntl = 0; ntl < 8; ntl++){
            int c0 = wn*64 + ntl*8 + 2*tid;
            float b2a = bs2[c0], b2b = bs2[c0+1];
            float2 s0 = *(const float2*)&g_state[r0*HH + c0];
            float2 s1 = *(const float2*)&g_state[r1*HH + c0];
            float2 v0 = make_float2(s0.x + e2[ntl][0] + b2a, s0.y + e2[ntl][1] + b2b);
            float2 v1 = make_float2(s1.x + e2[ntl][2] + b2a, s1.y + e2[ntl][3] + b2b);
            *(float2*)&g_state[r0*HH + c0] = v0;
            *(float2*)&g_state[r1*HH + c0] = v1;
            *(float2*)&out[r0*HH + c0] = v0;
            *(float2*)&out[r1*HH + c0] = v1;
        }
    }
}

// ---------------------------------------------------------------------------
extern "C" void kernel_launch(void* const* d_in, const int* in_sizes, int n_in,
                              void* d_out, int out_size)
{
    const int*   nodes      = (const int*)  d_in[0];
    const int*   atom_edges = (const int*)  d_in[1];
    const float* feats      = (const float*)d_in[2];
    const int*   num_nodes  = (const int*)  d_in[3];
    // d_in[4] = num_atom_edges (all == EP, unused)
    const float* emb = (const float*)d_in[5];
    const float* Wn1 = (const float*)d_in[6];
    const float* bn1 = (const float*)d_in[7];
    const float* Wn2 = (const float*)d_in[8];
    const float* bn2 = (const float*)d_in[9];
    const float* We1 = (const float*)d_in[10];
    const float* be1 = (const float*)d_in[11];
    const float* We2 = (const float*)d_in[12];
    const float* be2 = (const float*)d_in[13];
    const float* Ws1 = (const float*)d_in[14];
    const float* bs1 = (const float*)d_in[15];
    const float* Ws2 = (const float*)d_in[16];
    const float* bs2 = (const float*)d_in[17];
    float* out = (float*)d_out;

    cudaFuncSetAttribute(k_edge, cudaFuncAttributeMaxDynamicSharedMemorySize,
                         SMEM_WORDS*sizeof(unsigned));
    cudaFuncSetAttribute(k_pre, cudaFuncAttributeMaxDynamicSharedMemorySize,
                         SMEM_PRE*sizeof(unsigned));
    cudaFuncSetAttribute(k_upd, cudaFuncAttributeMaxDynamicSharedMemorySize,
                         SMEM_UPD*sizeof(unsigned));

    k_init<<<(NT*HH + 255)/256, 256>>>(nodes, emb, num_nodes);
    k_wt<<<384, 256>>>(Wn1, Ws1, Ws2);
    for (int l = 0; l < NL; l++){
        k_pre<<<NT/64, 256, SMEM_PRE*sizeof(unsigned)>>>(l);
        k_edge<<<GRID_EDGE, 256, SMEM_WORDS*sizeof(unsigned)>>>(atom_edges, feats,
            bn1 + l*HH, Wn2 + l*HH*HH, bn2 + l*HH,
            We1 + l*ES*HH, be1 + l*HH, We2 + l*HH*HH, be2 + l*HH);
        k_upd<<<NT/64, 256, SMEM_UPD*sizeof(unsigned)>>>(l, bs1 + l*HH, bs2 + l*HH,
                              out + (size_t)l*NT*HH);
    }
}